// round 1
// baseline (speedup 1.0000x reference)
#include <cuda_runtime.h>

// ---------------------------------------------------------------------------
// Problem constants
// ---------------------------------------------------------------------------
#define B_    8
#define NH    8
#define HD    48
#define HW    64
#define NPIX  4096            // 64*64
#define C_    384
#define M_    32768           // B_*NPIX
#define L_    277             // 1 + 4 + 16 + 256
#define QKN   1152            // 3*C_

// ---------------------------------------------------------------------------
// Scratch (allocation-free rule: __device__ globals)
// ---------------------------------------------------------------------------
__device__ float g_q [M_ * C_];           // [b*N+n, h*48+d]
__device__ float g_k [M_ * C_];
__device__ float g_v [M_ * C_];
__device__ float g_ao[M_ * C_];           // attention output, [b*N+n, h*48+d]
__device__ float g_kp[B_ * NH * L_ * HD]; // [bh, l, d]
__device__ float g_vp[B_ * NH * L_ * HD];

// ---------------------------------------------------------------------------
// SGEMM: 128x128 block, BK=8, 256 threads, 8x8 per-thread micro-tile.
// mode 0: A = Ain (x), C scattered to g_q/g_k/g_v (column block picks matrix,
//         since 1152 = 9*128 and 384 = 3*128 the split is per-block uniform).
// mode 1: A = g_ao, C = Cout (+bias).
// ---------------------------------------------------------------------------
#define BM 128
#define BN 128
#define BK 8

__global__ void __launch_bounds__(256) sgemm_kernel(
    const float* __restrict__ Ain, const float* __restrict__ Bmat,
    float* __restrict__ Cout, const float* __restrict__ bias,
    int M, int N, int K, int mode)
{
    __shared__ float As[BK][BM];
    __shared__ float Bs[BK][BN];

    const float* A = (mode == 0) ? Ain : g_ao;

    float* Cbase;
    int coloff, ldc;
    if (mode == 0) {
        int t = (blockIdx.x * BN) / C_;            // 0,1,2 -> q,k,v
        Cbase  = (t == 0) ? g_q : (t == 1) ? g_k : g_v;
        coloff = blockIdx.x * BN - t * C_;
        ldc    = C_;
    } else {
        Cbase  = Cout;
        coloff = blockIdx.x * BN;
        ldc    = N;
    }

    const int tid = threadIdx.x;
    const int tx  = tid & 15;
    const int ty  = tid >> 4;

    const int aRow = tid >> 1;
    const int aK   = (tid & 1) << 2;
    const int bRow = tid >> 5;
    const int bCol = (tid & 31) << 2;

    const float* Aptr = A    + (size_t)(blockIdx.y * BM + aRow) * K + aK;
    const float* Bptr = Bmat + (size_t)bRow * N + blockIdx.x * BN + bCol;

    float acc[8][8];
    #pragma unroll
    for (int i = 0; i < 8; i++)
        #pragma unroll
        for (int j = 0; j < 8; j++) acc[i][j] = 0.f;

    const int kTiles = K / BK;
    float4 aReg = *(const float4*)Aptr;
    float4 bReg = *(const float4*)Bptr;

    for (int kt = 0; ; ) {
        As[aK + 0][aRow] = aReg.x;
        As[aK + 1][aRow] = aReg.y;
        As[aK + 2][aRow] = aReg.z;
        As[aK + 3][aRow] = aReg.w;
        *(float4*)&Bs[bRow][bCol] = bReg;
        __syncthreads();

        if (kt + 1 < kTiles) {
            aReg = *(const float4*)(Aptr + (kt + 1) * BK);
            bReg = *(const float4*)(Bptr + (size_t)(kt + 1) * BK * N);
        }

        #pragma unroll
        for (int kk = 0; kk < BK; kk++) {
            float4 a0 = *(const float4*)&As[kk][ty * 8];
            float4 a1 = *(const float4*)&As[kk][ty * 8 + 4];
            float4 b0 = *(const float4*)&Bs[kk][tx * 8];
            float4 b1 = *(const float4*)&Bs[kk][tx * 8 + 4];
            float af[8] = {a0.x, a0.y, a0.z, a0.w, a1.x, a1.y, a1.z, a1.w};
            float bf[8] = {b0.x, b0.y, b0.z, b0.w, b1.x, b1.y, b1.z, b1.w};
            #pragma unroll
            for (int i = 0; i < 8; i++)
                #pragma unroll
                for (int j = 0; j < 8; j++)
                    acc[i][j] += af[i] * bf[j];
        }
        __syncthreads();
        if (++kt == kTiles) break;
    }

    const int row0 = blockIdx.y * BM + ty * 8;
    const int col0 = coloff + tx * 8;
    #pragma unroll
    for (int i = 0; i < 8; i++) {
        float* crow = Cbase + (size_t)(row0 + i) * ldc + col0;
        float4 o0 = make_float4(acc[i][0], acc[i][1], acc[i][2], acc[i][3]);
        float4 o1 = make_float4(acc[i][4], acc[i][5], acc[i][6], acc[i][7]);
        if (bias) {
            o0.x += bias[col0 + 0]; o0.y += bias[col0 + 1];
            o0.z += bias[col0 + 2]; o0.w += bias[col0 + 3];
            o1.x += bias[col0 + 4]; o1.y += bias[col0 + 5];
            o1.z += bias[col0 + 6]; o1.w += bias[col0 + 7];
        }
        *(float4*)crow       = o0;
        *(float4*)(crow + 4) = o1;
    }
}

// ---------------------------------------------------------------------------
// Pyramid pooling stage 1: s=16 grid (4x4-pixel cells) straight from K/V.
// grid (256 cells, 64 bh), block 64 threads (48 active, d-coalesced).
// ---------------------------------------------------------------------------
__global__ void pool16_kernel()
{
    const int d = threadIdx.x;
    if (d >= HD) return;
    const int cell = blockIdx.x;         // ci*16 + cj
    const int bh   = blockIdx.y;
    const int b = bh >> 3, h = bh & 7;
    const int ci = cell >> 4, cj = cell & 15;

    float ks = 0.f, vs = 0.f;
    #pragma unroll
    for (int dy = 0; dy < 4; dy++)
        #pragma unroll
        for (int dx = 0; dx < 4; dx++) {
            int n = (ci * 4 + dy) * HW + (cj * 4 + dx);
            size_t off = (size_t)(b * NPIX + n) * C_ + h * HD + d;
            ks += g_k[off];
            vs += g_v[off];
        }
    size_t po = ((size_t)bh * L_ + 21 + cell) * HD + d;
    g_kp[po] = ks * (1.f / 16.f);
    g_vp[po] = vs * (1.f / 16.f);
}

// ---------------------------------------------------------------------------
// Pyramid pooling stage 2: derive s=4 (offset 5), s=2 (offset 1), s=1 (0)
// hierarchically from s=16 (offset 21). Exact: means of equal-size means.
// One block per bh; two passes (k then v).
// ---------------------------------------------------------------------------
__global__ void pool_rest_kernel()
{
    __shared__ float s4[16 * HD];
    __shared__ float s2[4 * HD];
    const int bh  = blockIdx.x;
    const int tid = threadIdx.x;

    for (int pass = 0; pass < 2; pass++) {
        float* base = (pass ? g_vp : g_kp) + (size_t)bh * L_ * HD;

        // s=4 : each cell averages a 4x4 block of s=16 cells
        for (int o = tid; o < 16 * HD; o += 256) {
            int cell = o / HD, d = o % HD;
            int I = cell >> 2, J = cell & 3;
            float s = 0.f;
            #pragma unroll
            for (int di = 0; di < 4; di++)
                #pragma unroll
                for (int dj = 0; dj < 4; dj++)
                    s += base[(21 + ((I * 4 + di) * 16 + (J * 4 + dj))) * HD + d];
            s *= (1.f / 16.f);
            s4[o] = s;
            base[(5 + cell) * HD + d] = s;
        }
        __syncthreads();

        // s=2 : 2x2 of s=4 cells
        for (int o = tid; o < 4 * HD; o += 256) {
            int cell = o / HD, d = o % HD;
            int I = cell >> 1, J = cell & 1;
            float s = 0.f;
            #pragma unroll
            for (int di = 0; di < 2; di++)
                #pragma unroll
                for (int dj = 0; dj < 2; dj++)
                    s += s4[((I * 2 + di) * 4 + (J * 2 + dj)) * HD + d];
            s *= 0.25f;
            s2[o] = s;
            base[(1 + cell) * HD + d] = s;
        }
        __syncthreads();

        // s=1
        for (int o = tid; o < HD; o += 256)
            base[o] = 0.25f * (s2[o] + s2[HD + o] + s2[2 * HD + o] + s2[3 * HD + o]);
        __syncthreads();
    }
}

// ---------------------------------------------------------------------------
// Attention: one thread = one query row. KP/VP for this (b,h) staged in SMEM
// (106 KB dynamic). Logits bounded (|s| <~ 2 since pooled K has var <= 1/16),
// so exp() without max-subtraction is safe -> single pass, no logits buffer.
// ---------------------------------------------------------------------------
__global__ void __launch_bounds__(256, 2) attn_kernel()
{
    extern __shared__ float sm[];
    float* kps = sm;                 // L_*HD floats
    float* vps = sm + L_ * HD;

    const int bh = blockIdx.y;
    const int b = bh >> 3, h = bh & 7;

    const float4* kpg = (const float4*)(g_kp + (size_t)bh * L_ * HD);
    const float4* vpg = (const float4*)(g_vp + (size_t)bh * L_ * HD);
    const int tot4 = (L_ * HD) / 4;  // 3324
    for (int i = threadIdx.x; i < tot4; i += 256) {
        ((float4*)kps)[i] = kpg[i];
        ((float4*)vps)[i] = vpg[i];
    }
    __syncthreads();

    const int n = blockIdx.x * 256 + threadIdx.x;
    const float* qrow = g_q + (size_t)(b * NPIX + n) * C_ + h * HD;
    const float scale = 0.14433756729740643f;   // 48^-0.5, folded into q

    float4 q[12];
    #pragma unroll
    for (int j = 0; j < 12; j++) {
        float4 t = ((const float4*)qrow)[j];
        t.x *= scale; t.y *= scale; t.z *= scale; t.w *= scale;
        q[j] = t;
    }

    float4 acc[12];
    #pragma unroll
    for (int j = 0; j < 12; j++) acc[j] = make_float4(0.f, 0.f, 0.f, 0.f);
    float ssum = 0.f;

    for (int l = 0; l < L_; l++) {
        const float4* kp4 = (const float4*)(kps + l * HD);
        float s0 = 0.f, s1 = 0.f, s2 = 0.f, s3 = 0.f;   // 4 chains for ILP
        #pragma unroll
        for (int j = 0; j < 12; j += 4) {
            float4 k0 = kp4[j], k1 = kp4[j + 1], k2 = kp4[j + 2], k3 = kp4[j + 3];
            s0 += q[j    ].x * k0.x + q[j    ].y * k0.y + q[j    ].z * k0.z + q[j    ].w * k0.w;
            s1 += q[j + 1].x * k1.x + q[j + 1].y * k1.y + q[j + 1].z * k1.z + q[j + 1].w * k1.w;
            s2 += q[j + 2].x * k2.x + q[j + 2].y * k2.y + q[j + 2].z * k2.z + q[j + 2].w * k2.w;
            s3 += q[j + 3].x * k3.x + q[j + 3].y * k3.y + q[j + 3].z * k3.z + q[j + 3].w * k3.w;
        }
        float e = __expf((s0 + s1) + (s2 + s3));
        ssum += e;
        const float4* vp4 = (const float4*)(vps + l * HD);
        #pragma unroll
        for (int j = 0; j < 12; j++) {
            float4 vv = vp4[j];
            acc[j].x += e * vv.x; acc[j].y += e * vv.y;
            acc[j].z += e * vv.z; acc[j].w += e * vv.w;
        }
    }

    const float inv = 1.f / ssum;
    float* orow = g_ao + (size_t)(b * NPIX + n) * C_ + h * HD;
    #pragma unroll
    for (int j = 0; j < 12; j++) {
        float4 o = acc[j];
        o.x *= inv; o.y *= inv; o.z *= inv; o.w *= inv;
        ((float4*)orow)[j] = o;
    }
}

// ---------------------------------------------------------------------------
// Entry point
// ---------------------------------------------------------------------------
extern "C" void kernel_launch(void* const* d_in, const int* in_sizes, int n_in,
                              void* d_out, int out_size)
{
    const float* x      = (const float*)d_in[0];
    const float* w_qkv  = (const float*)d_in[1];
    const float* w_proj = (const float*)d_in[2];
    const float* b_proj = (const float*)d_in[3];
    float* out = (float*)d_out;

    // attention kernel needs 106,368 B dynamic SMEM (> 48 KB default)
    cudaFuncSetAttribute(attn_kernel,
                         cudaFuncAttributeMaxDynamicSharedMemorySize,
                         2 * L_ * HD * (int)sizeof(float));

    // 1) QKV GEMM, scattered into g_q/g_k/g_v
    sgemm_kernel<<<dim3(QKN / BN, M_ / BM), 256>>>(
        x, w_qkv, nullptr, nullptr, M_, QKN, C_, 0);

    // 2) pyramid pooling
    pool16_kernel<<<dim3(256, B_ * NH), 64>>>();
    pool_rest_kernel<<<B_ * NH, 256>>>();

    // 3) attention
    attn_kernel<<<dim3(NPIX / 256, B_ * NH), 256,
                  2 * L_ * HD * sizeof(float)>>>();

    // 4) projection + bias -> d_out
    sgemm_kernel<<<dim3(C_ / BN, M_ / BM), 256>>>(
        nullptr, w_proj, out, b_proj, M_, C_, C_, 1);
}

// round 3
// speedup vs baseline: 1.5785x; 1.5785x over previous
#include <cuda_runtime.h>
#include <cuda_bf16.h>
#include <cstdint>

// ---------------------------------------------------------------------------
// Problem constants
// ---------------------------------------------------------------------------
#define B_    8
#define NH    8
#define HD    48
#define HW    64
#define NPIX  4096            // 64*64
#define C_    384
#define M_    32768           // B_*NPIX
#define L_    277             // 1 + 4 + 16 + 256
#define QKN   1152            // 3*C_

// ---------------------------------------------------------------------------
// Scratch (allocation-free rule: __device__ globals)
// ---------------------------------------------------------------------------
__device__ float g_q [M_ * C_];           // [b*N+n, h*48+d]
__device__ float g_k [M_ * C_];
__device__ float g_v [M_ * C_];
__device__ float g_kp[B_ * NH * L_ * HD]; // [bh, l, d]
__device__ float g_vp[B_ * NH * L_ * HD];

// bf16 split operands for tensor-core GEMMs
__device__ __nv_bfloat16 g_xhi[M_ * C_];
__device__ __nv_bfloat16 g_xlo[M_ * C_];
__device__ __nv_bfloat16 g_wqT_hi[QKN * C_];   // w_qkv transposed: [1152, 384]
__device__ __nv_bfloat16 g_wqT_lo[QKN * C_];
__device__ __nv_bfloat16 g_wpT_hi[C_ * C_];    // w_proj transposed: [384, 384]
__device__ __nv_bfloat16 g_wpT_lo[C_ * C_];
__device__ __nv_bfloat16 g_aohi[M_ * C_];      // attention output, split
__device__ __nv_bfloat16 g_aolo[M_ * C_];

// ---------------------------------------------------------------------------
// Warp MMA helpers (sm_80+ PTX; no 'a'-suffix features)
// ---------------------------------------------------------------------------
__device__ __forceinline__ uint32_t smem_u32(const void* p) {
    uint32_t a;
    asm("{ .reg .u64 t; cvta.to.shared.u64 t, %1; cvt.u32.u64 %0, t; }"
        : "=r"(a) : "l"(p));
    return a;
}
__device__ __forceinline__ void ldm_x4(uint32_t* r, uint32_t addr) {
    asm volatile("ldmatrix.sync.aligned.m8n8.x4.shared.b16 {%0,%1,%2,%3}, [%4];"
        : "=r"(r[0]), "=r"(r[1]), "=r"(r[2]), "=r"(r[3]) : "r"(addr));
}
__device__ __forceinline__ void mma_bf16(float* c, const uint32_t* a,
                                         const uint32_t* b) {
    asm volatile(
        "mma.sync.aligned.m16n8k16.row.col.f32.bf16.bf16.f32 "
        "{%0,%1,%2,%3}, {%4,%5,%6,%7}, {%8,%9}, {%0,%1,%2,%3};"
        : "+f"(c[0]), "+f"(c[1]), "+f"(c[2]), "+f"(c[3])
        : "r"(a[0]), "r"(a[1]), "r"(a[2]), "r"(a[3]), "r"(b[0]), "r"(b[1]));
}

// ---------------------------------------------------------------------------
// Convert x (fp32) -> bf16 hi/lo
// ---------------------------------------------------------------------------
__global__ void conv_x_kernel(const float* __restrict__ x)
{
    int i = blockIdx.x * blockDim.x + threadIdx.x;          // per float4
    float4 v = ((const float4*)x)[i];
    __nv_bfloat162 h01 = __floats2bfloat162_rn(v.x, v.y);
    __nv_bfloat162 h23 = __floats2bfloat162_rn(v.z, v.w);
    __nv_bfloat162 l01 = __floats2bfloat162_rn(v.x - __low2float(h01),
                                               v.y - __high2float(h01));
    __nv_bfloat162 l23 = __floats2bfloat162_rn(v.z - __low2float(h23),
                                               v.w - __high2float(h23));
    ((__nv_bfloat162*)g_xhi)[i * 2    ] = h01;
    ((__nv_bfloat162*)g_xhi)[i * 2 + 1] = h23;
    ((__nv_bfloat162*)g_xlo)[i * 2    ] = l01;
    ((__nv_bfloat162*)g_xlo)[i * 2 + 1] = l23;
}

// ---------------------------------------------------------------------------
// Convert + transpose weights: w[K,N] -> wT[N,K] bf16 hi/lo
// ---------------------------------------------------------------------------
__global__ void conv_w_kernel(const float* __restrict__ wqkv,
                              const float* __restrict__ wp)
{
    int i = blockIdx.x * blockDim.x + threadIdx.x;
    const int NQ = QKN * C_;                 // 442368
    if (i < NQ) {
        int n = i / C_, k = i % C_;
        float v = wqkv[(size_t)k * QKN + n];
        __nv_bfloat16 h = __float2bfloat16(v);
        g_wqT_hi[i] = h;
        g_wqT_lo[i] = __float2bfloat16(v - __bfloat162float(h));
    } else {
        int j = i - NQ;
        if (j < C_ * C_) {
            int n = j / C_, k = j % C_;
            float v = wp[(size_t)k * C_ + n];
            __nv_bfloat16 h = __float2bfloat16(v);
            g_wpT_hi[j] = h;
            g_wpT_lo[j] = __float2bfloat16(v - __bfloat162float(h));
        }
    }
}

// ---------------------------------------------------------------------------
// Tensor-core GEMM via mma.sync (bf16 3-term split, fp32 accumulate).
//   C[M,N] = A[M,384] * B^T, B stored [N,384] (k contiguous == col-major frag)
// Block 128x128, 8 warps in a 4x2 grid, warp tile 32x64, BK = 32.
// mode 0: A = g_x{hi,lo}, B = g_wqT  -> scatter into g_q/g_k/g_v
// mode 1: A = g_ao{hi,lo}, B = g_wpT -> Cout + bias
// ---------------------------------------------------------------------------
#define ASTRIDE 40     // bf16 elems per SMEM row (32 data + 8 pad) = 80 B

__global__ void __launch_bounds__(256) gemm_mma_kernel(
    float* __restrict__ Cout, const float* __restrict__ bias, int mode)
{
    __shared__ __nv_bfloat16 sAh[128 * ASTRIDE];
    __shared__ __nv_bfloat16 sAl[128 * ASTRIDE];
    __shared__ __nv_bfloat16 sBh[128 * ASTRIDE];
    __shared__ __nv_bfloat16 sBl[128 * ASTRIDE];

    const int tid  = threadIdx.x;
    const int lane = tid & 31;
    const int wid  = tid >> 5;
    const int wm   = wid & 3;        // 4 warps along M
    const int wn   = wid >> 2;       // 2 warps along N

    const __nv_bfloat16* Ahi = (mode == 0) ? g_xhi : g_aohi;
    const __nv_bfloat16* Alo = (mode == 0) ? g_xlo : g_aolo;
    const __nv_bfloat16* Bhi = (mode == 0) ? g_wqT_hi : g_wpT_hi;
    const __nv_bfloat16* Blo = (mode == 0) ? g_wqT_lo : g_wpT_lo;

    const int row0 = blockIdx.y * 128;
    const int col0 = blockIdx.x * 128;

    float acc[2][8][4];
    #pragma unroll
    for (int mt = 0; mt < 2; mt++)
        #pragma unroll
        for (int nt = 0; nt < 8; nt++)
            #pragma unroll
            for (int e = 0; e < 4; e++) acc[mt][nt][e] = 0.f;

    // precomputed ldmatrix SMEM lane offsets (element units)
    const int aRow = (lane & 15);
    const int aKof = (lane >> 4) * 8;
    const int bRow = (lane & 7) + ((lane >> 3) & 1) * 8;
    const int bKof = (lane >> 4) * 8;

    for (int c = 0; c < 12; c++) {
        const int koff = c * 32;
        // ---- global -> SMEM: 4 tiles of 128 rows x 32 bf16 (64 B) ----
        #pragma unroll
        for (int j0 = 0; j0 < 2; j0++) {
            int j = tid * 2 + j0;            // 0..511
            int r = j >> 2, q = j & 3;
            size_t goA = (size_t)(row0 + r) * C_ + koff;
            size_t goB = (size_t)(col0 + r) * C_ + koff;
            uint4 vah = ((const uint4*)(Ahi + goA))[q];
            uint4 val = ((const uint4*)(Alo + goA))[q];
            uint4 vbh = ((const uint4*)(Bhi + goB))[q];
            uint4 vbl = ((const uint4*)(Blo + goB))[q];
            int so = r * ASTRIDE + q * 8;
            *(uint4*)&sAh[so] = vah;
            *(uint4*)&sAl[so] = val;
            *(uint4*)&sBh[so] = vbh;
            *(uint4*)&sBl[so] = vbl;
        }
        __syncthreads();

        // ---- MMAs over 2 k-steps of 16 ----
        #pragma unroll
        for (int ks = 0; ks < 2; ks++) {
            const int kk = ks * 16;
            uint32_t ah[2][4], al[2][4];
            #pragma unroll
            for (int mt = 0; mt < 2; mt++) {
                int so = (wm * 32 + mt * 16 + aRow) * ASTRIDE + kk + aKof;
                ldm_x4(ah[mt], smem_u32(&sAh[so]));
                ldm_x4(al[mt], smem_u32(&sAl[so]));
            }
            uint32_t bh[8][2], bl[8][2];
            #pragma unroll
            for (int np = 0; np < 4; np++) {     // pairs of 8-wide n-tiles
                int so = (wn * 64 + np * 16 + bRow) * ASTRIDE + kk + bKof;
                uint32_t t[4];
                ldm_x4(t, smem_u32(&sBh[so]));
                bh[np * 2    ][0] = t[0]; bh[np * 2    ][1] = t[2];
                bh[np * 2 + 1][0] = t[1]; bh[np * 2 + 1][1] = t[3];
                ldm_x4(t, smem_u32(&sBl[so]));
                bl[np * 2    ][0] = t[0]; bl[np * 2    ][1] = t[2];
                bl[np * 2 + 1][0] = t[1]; bl[np * 2 + 1][1] = t[3];
            }
            #pragma unroll
            for (int mt = 0; mt < 2; mt++)
                #pragma unroll
                for (int nt = 0; nt < 8; nt++) {
                    mma_bf16(acc[mt][nt], ah[mt], bh[nt]);   // hi*hi
                    mma_bf16(acc[mt][nt], ah[mt], bl[nt]);   // hi*lo
                    mma_bf16(acc[mt][nt], al[mt], bh[nt]);   // lo*hi
                }
        }
        __syncthreads();
    }

    // ---- epilogue ----
    float* Cbase;
    int coff;
    if (mode == 0) {
        int t = col0 / C_;                    // 0,1,2 -> q,k,v
        Cbase = (t == 0) ? g_q : (t == 1) ? g_k : g_v;
        coff  = col0 - t * C_;
    } else {
        Cbase = Cout;
        coff  = col0;
    }
    const int mrow = row0 + wm * 32 + (lane >> 2);
    const int ncol = coff + wn * 64 + (lane & 3) * 2;

    #pragma unroll
    for (int mt = 0; mt < 2; mt++)
        #pragma unroll
        for (int nt = 0; nt < 8; nt++) {
            int r = mrow + mt * 16;
            int cc = ncol + nt * 8;
            float2 v0 = make_float2(acc[mt][nt][0], acc[mt][nt][1]);
            float2 v1 = make_float2(acc[mt][nt][2], acc[mt][nt][3]);
            if (mode == 1) {
                v0.x += bias[cc]; v0.y += bias[cc + 1];
                v1.x += bias[cc]; v1.y += bias[cc + 1];
            }
            *(float2*)&Cbase[(size_t)r * C_ + cc]       = v0;
            *(float2*)&Cbase[(size_t)(r + 8) * C_ + cc] = v1;
        }
}

// ---------------------------------------------------------------------------
// Pyramid pooling stage 1: s=16 grid (4x4-pixel cells) straight from K/V.
// ---------------------------------------------------------------------------
__global__ void pool16_kernel()
{
    const int d = threadIdx.x;
    if (d >= HD) return;
    const int cell = blockIdx.x;
    const int bh   = blockIdx.y;
    const int b = bh >> 3, h = bh & 7;
    const int ci = cell >> 4, cj = cell & 15;

    float ks = 0.f, vs = 0.f;
    #pragma unroll
    for (int dy = 0; dy < 4; dy++)
        #pragma unroll
        for (int dx = 0; dx < 4; dx++) {
            int n = (ci * 4 + dy) * HW + (cj * 4 + dx);
            size_t off = (size_t)(b * NPIX + n) * C_ + h * HD + d;
            ks += g_k[off];
            vs += g_v[off];
        }
    size_t po = ((size_t)bh * L_ + 21 + cell) * HD + d;
    g_kp[po] = ks * (1.f / 16.f);
    g_vp[po] = vs * (1.f / 16.f);
}

// ---------------------------------------------------------------------------
// Pyramid pooling stage 2: derive s=4/2/1 hierarchically from s=16.
// ---------------------------------------------------------------------------
__global__ void pool_rest_kernel()
{
    __shared__ float s4[16 * HD];
    __shared__ float s2[4 * HD];
    const int bh  = blockIdx.x;
    const int tid = threadIdx.x;

    for (int pass = 0; pass < 2; pass++) {
        float* base = (pass ? g_vp : g_kp) + (size_t)bh * L_ * HD;

        for (int o = tid; o < 16 * HD; o += 256) {
            int cell = o / HD, d = o % HD;
            int I = cell >> 2, J = cell & 3;
            float s = 0.f;
            #pragma unroll
            for (int di = 0; di < 4; di++)
                #pragma unroll
                for (int dj = 0; dj < 4; dj++)
                    s += base[(21 + ((I * 4 + di) * 16 + (J * 4 + dj))) * HD + d];
            s *= (1.f / 16.f);
            s4[o] = s;
            base[(5 + cell) * HD + d] = s;
        }
        __syncthreads();

        for (int o = tid; o < 4 * HD; o += 256) {
            int cell = o / HD, d = o % HD;
            int I = cell >> 1, J = cell & 1;
            float s = 0.f;
            #pragma unroll
            for (int di = 0; di < 2; di++)
                #pragma unroll
                for (int dj = 0; dj < 2; dj++)
                    s += s4[((I * 2 + di) * 4 + (J * 2 + dj)) * HD + d];
            s *= 0.25f;
            s2[o] = s;
            base[(1 + cell) * HD + d] = s;
        }
        __syncthreads();

        for (int o = tid; o < HD; o += 256)
            base[o] = 0.25f * (s2[o] + s2[HD + o] + s2[2 * HD + o] + s2[3 * HD + o]);
        __syncthreads();
    }
}

// ---------------------------------------------------------------------------
// Attention: one thread = one query row; KP/VP staged in SMEM (106 KB).
// Writes output directly as bf16 hi/lo for the projection GEMM.
// ---------------------------------------------------------------------------
__global__ void __launch_bounds__(256, 2) attn_kernel()
{
    extern __shared__ float sm[];
    float* kps = sm;
    float* vps = sm + L_ * HD;

    const int bh = blockIdx.y;
    const int b = bh >> 3, h = bh & 7;

    const float4* kpg = (const float4*)(g_kp + (size_t)bh * L_ * HD);
    const float4* vpg = (const float4*)(g_vp + (size_t)bh * L_ * HD);
    const int tot4 = (L_ * HD) / 4;
    for (int i = threadIdx.x; i < tot4; i += 256) {
        ((float4*)kps)[i] = kpg[i];
        ((float4*)vps)[i] = vpg[i];
    }
    __syncthreads();

    const int n = blockIdx.x * 256 + threadIdx.x;
    const float* qrow = g_q + (size_t)(b * NPIX + n) * C_ + h * HD;
    const float scale = 0.14433756729740643f;   // 48^-0.5

    float4 q[12];
    #pragma unroll
    for (int j = 0; j < 12; j++) {
        float4 t = ((const float4*)qrow)[j];
        t.x *= scale; t.y *= scale; t.z *= scale; t.w *= scale;
        q[j] = t;
    }

    float4 acc[12];
    #pragma unroll
    for (int j = 0; j < 12; j++) acc[j] = make_float4(0.f, 0.f, 0.f, 0.f);
    float ssum = 0.f;

    for (int l = 0; l < L_; l++) {
        const float4* kp4 = (const float4*)(kps + l * HD);
        float s0 = 0.f, s1 = 0.f, s2 = 0.f, s3 = 0.f;
        #pragma unroll
        for (int j = 0; j < 12; j += 4) {
            float4 k0 = kp4[j], k1 = kp4[j + 1], k2 = kp4[j + 2], k3 = kp4[j + 3];
            s0 += q[j    ].x * k0.x + q[j    ].y * k0.y + q[j    ].z * k0.z + q[j    ].w * k0.w;
            s1 += q[j + 1].x * k1.x + q[j + 1].y * k1.y + q[j + 1].z * k1.z + q[j + 1].w * k1.w;
            s2 += q[j + 2].x * k2.x + q[j + 2].y * k2.y + q[j + 2].z * k2.z + q[j + 2].w * k2.w;
            s3 += q[j + 3].x * k3.x + q[j + 3].y * k3.y + q[j + 3].z * k3.z + q[j + 3].w * k3.w;
        }
        float e = __expf((s0 + s1) + (s2 + s3));
        ssum += e;
        const float4* vp4 = (const float4*)(vps + l * HD);
        #pragma unroll
        for (int j = 0; j < 12; j++) {
            float4 vv = vp4[j];
            acc[j].x += e * vv.x; acc[j].y += e * vv.y;
            acc[j].z += e * vv.z; acc[j].w += e * vv.w;
        }
    }

    const float inv = 1.f / ssum;
    const size_t rowoff = (size_t)(b * NPIX + n) * C_ + h * HD;
    __nv_bfloat162* hrow = (__nv_bfloat162*)(g_aohi + rowoff);
    __nv_bfloat162* lrow = (__nv_bfloat162*)(g_aolo + rowoff);
    #pragma unroll
    for (int j = 0; j < 12; j++) {
        float4 o = acc[j];
        o.x *= inv; o.y *= inv; o.z *= inv; o.w *= inv;
        __nv_bfloat162 h01 = __floats2bfloat162_rn(o.x, o.y);
        __nv_bfloat162 h23 = __floats2bfloat162_rn(o.z, o.w);
        __nv_bfloat162 l01 = __floats2bfloat162_rn(o.x - __low2float(h01),
                                                   o.y - __high2float(h01));
        __nv_bfloat162 l23 = __floats2bfloat162_rn(o.z - __low2float(h23),
                                                   o.w - __high2float(h23));
        hrow[j * 2    ] = h01;
        hrow[j * 2 + 1] = h23;
        lrow[j * 2    ] = l01;
        lrow[j * 2 + 1] = l23;
    }
}

// ---------------------------------------------------------------------------
// Entry point
// ---------------------------------------------------------------------------
extern "C" void kernel_launch(void* const* d_in, const int* in_sizes, int n_in,
                              void* d_out, int out_size)
{
    const float* x      = (const float*)d_in[0];
    const float* w_qkv  = (const float*)d_in[1];
    const float* w_proj = (const float*)d_in[2];
    const float* b_proj = (const float*)d_in[3];
    float* out = (float*)d_out;

    cudaFuncSetAttribute(attn_kernel,
                         cudaFuncAttributeMaxDynamicSharedMemorySize,
                         2 * L_ * HD * (int)sizeof(float));

    // 0) fp32 -> bf16 hi/lo conversions
    conv_x_kernel<<<(M_ * C_ / 4) / 256, 256>>>(x);
    conv_w_kernel<<<(QKN * C_ + C_ * C_ + 255) / 256, 256>>>(w_qkv, w_proj);

    // 1) QKV GEMM (tensor cores, 3-term bf16 split) -> g_q/g_k/g_v
    gemm_mma_kernel<<<dim3(QKN / 128, M_ / 128), 256>>>(nullptr, nullptr, 0);

    // 2) pyramid pooling
    pool16_kernel<<<dim3(256, B_ * NH), 64>>>();
    pool_rest_kernel<<<B_ * NH, 256>>>();

    // 3) attention (writes ao hi/lo bf16)
    attn_kernel<<<dim3(NPIX / 256, B_ * NH), 256,
                  2 * L_ * HD * sizeof(float)>>>();

    // 4) projection + bias -> d_out (tensor cores)
    gemm_mma_kernel<<<dim3(C_ / 128, M_ / 128), 256>>>(out, b_proj, 1);
}

// round 5
// speedup vs baseline: 2.1793x; 1.3806x over previous
#include <cuda_runtime.h>
#include <cuda_bf16.h>
#include <cstdint>

// ---------------------------------------------------------------------------
// Problem constants
// ---------------------------------------------------------------------------
#define B_    8
#define NH    8
#define HD    48
#define HW    64
#define NPIX  4096            // 64*64
#define C_    384
#define M_    32768           // B_*NPIX
#define L_    277             // 1 + 4 + 16 + 256
#define LP    288             // padded L (9 chunks of 32)
#define QKN   1152            // 3*C_

// scale * log2(e) folded into q so logits are in log2 domain
#define QSC   0.2082351519f

// ---------------------------------------------------------------------------
// Scratch (allocation-free rule: __device__ globals)
// ---------------------------------------------------------------------------
__device__ float g_k [M_ * C_];
__device__ float g_v [M_ * C_];
__device__ float g_kp[B_ * NH * L_ * HD]; // [bh, l, d] fp32
__device__ float g_vp[B_ * NH * L_ * HD];

__device__ __nv_bfloat16 g_qhi[M_ * C_];       // q * QSC, split
__device__ __nv_bfloat16 g_qlo[M_ * C_];
__device__ __nv_bfloat16 g_xhi[M_ * C_];
__device__ __nv_bfloat16 g_xlo[M_ * C_];
__device__ __nv_bfloat16 g_wqT_hi[QKN * C_];   // w_qkv transposed: [1152, 384]
__device__ __nv_bfloat16 g_wqT_lo[QKN * C_];
__device__ __nv_bfloat16 g_wpT_hi[C_ * C_];    // w_proj transposed: [384, 384]
__device__ __nv_bfloat16 g_wpT_lo[C_ * C_];
__device__ __nv_bfloat16 g_aohi[M_ * C_];      // attention output, split
__device__ __nv_bfloat16 g_aolo[M_ * C_];

__device__ __nv_bfloat16 g_kphi[B_ * NH * LP * HD];   // [bh][l(288)][d]
__device__ __nv_bfloat16 g_kplo[B_ * NH * LP * HD];
__device__ __nv_bfloat16 g_vpthi[B_ * NH * HD * LP];  // [bh][d][l(288)]
__device__ __nv_bfloat16 g_vptlo[B_ * NH * HD * LP];

// ---------------------------------------------------------------------------
// Warp MMA helpers (sm_80+ PTX; no 'a'-suffix features)
// ---------------------------------------------------------------------------
__device__ __forceinline__ uint32_t smem_u32(const void* p) {
    uint32_t a;
    asm("{ .reg .u64 t; cvta.to.shared.u64 t, %1; cvt.u32.u64 %0, t; }"
        : "=r"(a) : "l"(p));
    return a;
}
__device__ __forceinline__ void ldm_x4(uint32_t* r, uint32_t addr) {
    asm volatile("ldmatrix.sync.aligned.m8n8.x4.shared.b16 {%0,%1,%2,%3}, [%4];"
        : "=r"(r[0]), "=r"(r[1]), "=r"(r[2]), "=r"(r[3]) : "r"(addr));
}
__device__ __forceinline__ void mma_bf16(float* c, const uint32_t* a,
                                         const uint32_t* b) {
    asm volatile(
        "mma.sync.aligned.m16n8k16.row.col.f32.bf16.bf16.f32 "
        "{%0,%1,%2,%3}, {%4,%5,%6,%7}, {%8,%9}, {%0,%1,%2,%3};"
        : "+f"(c[0]), "+f"(c[1]), "+f"(c[2]), "+f"(c[3])
        : "r"(a[0]), "r"(a[1]), "r"(a[2]), "r"(a[3]), "r"(b[0]), "r"(b[1]));
}
__device__ __forceinline__ float ex2f(float x) {
    float r;
    asm("ex2.approx.f32 %0, %1;" : "=f"(r) : "f"(x));
    return r;
}
__device__ __forceinline__ void split_pack(float a, float b,
                                           uint32_t& hi, uint32_t& lo) {
    __nv_bfloat162 h = __floats2bfloat162_rn(a, b);
    __nv_bfloat162 l = __floats2bfloat162_rn(a - __low2float(h),
                                             b - __high2float(h));
    hi = *(uint32_t*)&h;
    lo = *(uint32_t*)&l;
}

// ---------------------------------------------------------------------------
// Convert x (fp32) -> bf16 hi/lo
// ---------------------------------------------------------------------------
__global__ void conv_x_kernel(const float* __restrict__ x)
{
    int i = blockIdx.x * blockDim.x + threadIdx.x;          // per float4
    float4 v = ((const float4*)x)[i];
    uint32_t h0, l0, h1, l1;
    split_pack(v.x, v.y, h0, l0);
    split_pack(v.z, v.w, h1, l1);
    ((uint32_t*)g_xhi)[i * 2    ] = h0;
    ((uint32_t*)g_xhi)[i * 2 + 1] = h1;
    ((uint32_t*)g_xlo)[i * 2    ] = l0;
    ((uint32_t*)g_xlo)[i * 2 + 1] = l1;
}

// ---------------------------------------------------------------------------
// Convert + transpose weights: w[K,N] -> wT[N,K] bf16 hi/lo
// ---------------------------------------------------------------------------
__global__ void conv_w_kernel(const float* __restrict__ wqkv,
                              const float* __restrict__ wp)
{
    int i = blockIdx.x * blockDim.x + threadIdx.x;
    const int NQ = QKN * C_;
    if (i < NQ) {
        int n = i / C_, k = i % C_;
        float v = wqkv[(size_t)k * QKN + n];
        __nv_bfloat16 h = __float2bfloat16(v);
        g_wqT_hi[i] = h;
        g_wqT_lo[i] = __float2bfloat16(v - __bfloat162float(h));
    } else {
        int j = i - NQ;
        if (j < C_ * C_) {
            int n = j / C_, k = j % C_;
            float v = wp[(size_t)k * C_ + n];
            __nv_bfloat16 h = __float2bfloat16(v);
            g_wpT_hi[j] = h;
            g_wpT_lo[j] = __float2bfloat16(v - __bfloat162float(h));
        }
    }
}

// ---------------------------------------------------------------------------
// Tensor-core GEMM via mma.sync (bf16 3-term split, fp32 accumulate).
//   C[M,N] = A[M,384] * B^T, B stored [N,384]
// Block 128x128, 8 warps (4x2), warp tile 32x64, BK = 32.
// mode 0: A = g_x{hi,lo}, B = g_wqT  -> q as bf16 hi/lo (scaled), k/v fp32
// mode 1: A = g_ao{hi,lo}, B = g_wpT -> Cout + bias
// ---------------------------------------------------------------------------
#define ASTRIDE 40     // bf16 elems per SMEM row (32 data + 8 pad)

__global__ void __launch_bounds__(256) gemm_mma_kernel(
    float* __restrict__ Cout, const float* __restrict__ bias, int mode)
{
    __shared__ __nv_bfloat16 sAh[128 * ASTRIDE];
    __shared__ __nv_bfloat16 sAl[128 * ASTRIDE];
    __shared__ __nv_bfloat16 sBh[128 * ASTRIDE];
    __shared__ __nv_bfloat16 sBl[128 * ASTRIDE];

    const int tid  = threadIdx.x;
    const int lane = tid & 31;
    const int wid  = tid >> 5;
    const int wm   = wid & 3;
    const int wn   = wid >> 2;

    const __nv_bfloat16* Ahi = (mode == 0) ? g_xhi : g_aohi;
    const __nv_bfloat16* Alo = (mode == 0) ? g_xlo : g_aolo;
    const __nv_bfloat16* Bhi = (mode == 0) ? g_wqT_hi : g_wpT_hi;
    const __nv_bfloat16* Blo = (mode == 0) ? g_wqT_lo : g_wpT_lo;

    const int row0 = blockIdx.y * 128;
    const int col0 = blockIdx.x * 128;

    float acc[2][8][4];
    #pragma unroll
    for (int mt = 0; mt < 2; mt++)
        #pragma unroll
        for (int nt = 0; nt < 8; nt++)
            #pragma unroll
            for (int e = 0; e < 4; e++) acc[mt][nt][e] = 0.f;

    const int aRow = (lane & 15);
    const int aKof = (lane >> 4) * 8;
    const int bRow = (lane & 7) + ((lane >> 3) & 1) * 8;
    const int bKof = (lane >> 4) * 8;

    for (int c = 0; c < 12; c++) {
        const int koff = c * 32;
        #pragma unroll
        for (int j0 = 0; j0 < 2; j0++) {
            int j = tid * 2 + j0;
            int r = j >> 2, q = j & 3;
            size_t goA = (size_t)(row0 + r) * C_ + koff;
            size_t goB = (size_t)(col0 + r) * C_ + koff;
            uint4 vah = ((const uint4*)(Ahi + goA))[q];
            uint4 val = ((const uint4*)(Alo + goA))[q];
            uint4 vbh = ((const uint4*)(Bhi + goB))[q];
            uint4 vbl = ((const uint4*)(Blo + goB))[q];
            int so = r * ASTRIDE + q * 8;
            *(uint4*)&sAh[so] = vah;
            *(uint4*)&sAl[so] = val;
            *(uint4*)&sBh[so] = vbh;
            *(uint4*)&sBl[so] = vbl;
        }
        __syncthreads();

        #pragma unroll
        for (int ks = 0; ks < 2; ks++) {
            const int kk = ks * 16;
            uint32_t ah[2][4], al[2][4];
            #pragma unroll
            for (int mt = 0; mt < 2; mt++) {
                int so = (wm * 32 + mt * 16 + aRow) * ASTRIDE + kk + aKof;
                ldm_x4(ah[mt], smem_u32(&sAh[so]));
                ldm_x4(al[mt], smem_u32(&sAl[so]));
            }
            uint32_t bh[8][2], bl[8][2];
            #pragma unroll
            for (int np = 0; np < 4; np++) {
                int so = (wn * 64 + np * 16 + bRow) * ASTRIDE + kk + bKof;
                uint32_t t[4];
                ldm_x4(t, smem_u32(&sBh[so]));
                bh[np * 2    ][0] = t[0]; bh[np * 2    ][1] = t[2];
                bh[np * 2 + 1][0] = t[1]; bh[np * 2 + 1][1] = t[3];
                ldm_x4(t, smem_u32(&sBl[so]));
                bl[np * 2    ][0] = t[0]; bl[np * 2    ][1] = t[2];
                bl[np * 2 + 1][0] = t[1]; bl[np * 2 + 1][1] = t[3];
            }
            #pragma unroll
            for (int mt = 0; mt < 2; mt++)
                #pragma unroll
                for (int nt = 0; nt < 8; nt++) {
                    mma_bf16(acc[mt][nt], ah[mt], bh[nt]);
                    mma_bf16(acc[mt][nt], ah[mt], bl[nt]);
                    mma_bf16(acc[mt][nt], al[mt], bh[nt]);
                }
        }
        __syncthreads();
    }

    // ---- epilogue ----
    const int mrow = row0 + wm * 32 + (lane >> 2);
    const int ncol = wn * 64 + (lane & 3) * 2;

    if (mode == 0 && col0 < C_) {
        // q block: scale, split to bf16 hi/lo
        #pragma unroll
        for (int mt = 0; mt < 2; mt++)
            #pragma unroll
            for (int nt = 0; nt < 8; nt++) {
                int r  = mrow + mt * 16;
                int cc = col0 + ncol + nt * 8;
                uint32_t h0, l0, h1, l1;
                split_pack(acc[mt][nt][0] * QSC, acc[mt][nt][1] * QSC, h0, l0);
                split_pack(acc[mt][nt][2] * QSC, acc[mt][nt][3] * QSC, h1, l1);
                *(uint32_t*)&g_qhi[(size_t)r * C_ + cc]       = h0;
                *(uint32_t*)&g_qlo[(size_t)r * C_ + cc]       = l0;
                *(uint32_t*)&g_qhi[(size_t)(r + 8) * C_ + cc] = h1;
                *(uint32_t*)&g_qlo[(size_t)(r + 8) * C_ + cc] = l1;
            }
        return;
    }

    float* Cbase;
    int coff;
    if (mode == 0) {
        int t = col0 / C_;                    // 1,2 -> k,v
        Cbase = (t == 1) ? g_k : g_v;
        coff  = col0 - t * C_;
    } else {
        Cbase = Cout;
        coff  = col0;
    }
    #pragma unroll
    for (int mt = 0; mt < 2; mt++)
        #pragma unroll
        for (int nt = 0; nt < 8; nt++) {
            int r  = mrow + mt * 16;
            int cc = coff + ncol + nt * 8;
            float2 v0 = make_float2(acc[mt][nt][0], acc[mt][nt][1]);
            float2 v1 = make_float2(acc[mt][nt][2], acc[mt][nt][3]);
            if (mode == 1) {
                v0.x += bias[cc]; v0.y += bias[cc + 1];
                v1.x += bias[cc]; v1.y += bias[cc + 1];
            }
            *(float2*)&Cbase[(size_t)r * C_ + cc]       = v0;
            *(float2*)&Cbase[(size_t)(r + 8) * C_ + cc] = v1;
        }
}

// ---------------------------------------------------------------------------
// Pyramid pooling stage 1: s=16 grid (4x4-pixel cells) straight from K/V.
// ---------------------------------------------------------------------------
__global__ void pool16_kernel()
{
    const int d = threadIdx.x;
    if (d >= HD) return;
    const int cell = blockIdx.x;
    const int bh   = blockIdx.y;
    const int b = bh >> 3, h = bh & 7;
    const int ci = cell >> 4, cj = cell & 15;

    float ks = 0.f, vs = 0.f;
    #pragma unroll
    for (int dy = 0; dy < 4; dy++)
        #pragma unroll
        for (int dx = 0; dx < 4; dx++) {
            int n = (ci * 4 + dy) * HW + (cj * 4 + dx);
            size_t off = (size_t)(b * NPIX + n) * C_ + h * HD + d;
            ks += g_k[off];
            vs += g_v[off];
        }
    size_t po = ((size_t)bh * L_ + 21 + cell) * HD + d;
    g_kp[po] = ks * (1.f / 16.f);
    g_vp[po] = vs * (1.f / 16.f);
}

// ---------------------------------------------------------------------------
// Pyramid pooling stage 2: derive s=4/2/1 hierarchically from s=16.
// ---------------------------------------------------------------------------
__global__ void pool_rest_kernel()
{
    __shared__ float s4[16 * HD];
    __shared__ float s2[4 * HD];
    const int bh  = blockIdx.x;
    const int tid = threadIdx.x;

    for (int pass = 0; pass < 2; pass++) {
        float* base = (pass ? g_vp : g_kp) + (size_t)bh * L_ * HD;

        for (int o = tid; o < 16 * HD; o += 256) {
            int cell = o / HD, d = o % HD;
            int I = cell >> 2, J = cell & 3;
            float s = 0.f;
            #pragma unroll
            for (int di = 0; di < 4; di++)
                #pragma unroll
                for (int dj = 0; dj < 4; dj++)
                    s += base[(21 + ((I * 4 + di) * 16 + (J * 4 + dj))) * HD + d];
            s *= (1.f / 16.f);
            s4[o] = s;
            base[(5 + cell) * HD + d] = s;
        }
        __syncthreads();

        for (int o = tid; o < 4 * HD; o += 256) {
            int cell = o / HD, d = o % HD;
            int I = cell >> 1, J = cell & 1;
            float s = 0.f;
            #pragma unroll
            for (int di = 0; di < 2; di++)
                #pragma unroll
                for (int dj = 0; dj < 2; dj++)
                    s += s4[((I * 2 + di) * 4 + (J * 2 + dj)) * HD + d];
            s *= 0.25f;
            s2[o] = s;
            base[(1 + cell) * HD + d] = s;
        }
        __syncthreads();

        for (int o = tid; o < HD; o += 256)
            base[o] = 0.25f * (s2[o] + s2[HD + o] + s2[2 * HD + o] + s2[3 * HD + o]);
        __syncthreads();
    }
}

// ---------------------------------------------------------------------------
// KP/VP fp32 -> bf16 hi/lo; KP kept [l][d], VP transposed to [d][l]; L padded.
// grid = 64 bh, 256 threads.
// ---------------------------------------------------------------------------
__global__ void conv_kv_kernel()
{
    const int bh = blockIdx.x;
    const float* kp = g_kp + (size_t)bh * L_ * HD;
    const float* vp = g_vp + (size_t)bh * L_ * HD;

    for (int i = threadIdx.x; i < LP * HD; i += 256) {
        int l = i / HD, d = i % HD;
        float kv = (l < L_) ? kp[l * HD + d] : 0.f;
        float vv = (l < L_) ? vp[l * HD + d] : 0.f;
        __nv_bfloat16 kh = __float2bfloat16(kv);
        __nv_bfloat16 vh = __float2bfloat16(vv);
        size_t ko = (size_t)bh * LP * HD + l * HD + d;
        size_t vo = (size_t)bh * HD * LP + d * LP + l;
        g_kphi[ko]  = kh;
        g_kplo[ko]  = __float2bfloat16(kv - __bfloat162float(kh));
        g_vpthi[vo] = vh;
        g_vptlo[vo] = __float2bfloat16(vv - __bfloat162float(vh));
    }
}

// ---------------------------------------------------------------------------
// Tensor-core attention. One CTA = one (b,h) x 256 q rows; 8 warps x 32 rows.
// KP [l][d] and VPt [d][l] staged in SMEM as bf16 hi/lo; Q frags in registers.
// No-max softmax in log2 domain (scale*log2e pre-folded into q).
// ---------------------------------------------------------------------------
#define QSTRIDE 56          // 48 + 8 pad  (112 B rows -> conflict-free ldmatrix)
#define VSTRIDE 296         // 288 + 8 pad (592 B rows -> conflict-free ldmatrix)

#define SQH 0
#define SQL (SQH + 256 * QSTRIDE * 2)         // 28672
#define SKH (SQL + 256 * QSTRIDE * 2)         // 57344
#define SKL (SKH + LP * QSTRIDE * 2)          // + 32256
#define SVH (SKL + LP * QSTRIDE * 2)
#define SVL (SVH + HD * VSTRIDE * 2)          // + 28416
#define ATTN_SMEM (SVL + HD * VSTRIDE * 2)    // 178688 B

__global__ void __launch_bounds__(256, 1) attn_mma_kernel()
{
    extern __shared__ char sm[];

    const int tid  = threadIdx.x;
    const int lane = tid & 31;
    const int wid  = tid >> 5;
    const int bh   = blockIdx.y;
    const int b    = bh >> 3, h = bh & 7;
    const int n0   = blockIdx.x * 256;

    // ---- prologue: stage Q, KP, VPt into SMEM ----
    {
        const uint4* qh = (const uint4*)(g_qhi + (size_t)(b * NPIX + n0) * C_ + h * HD);
        const uint4* ql = (const uint4*)(g_qlo + (size_t)(b * NPIX + n0) * C_ + h * HD);
        for (int i = tid; i < 256 * 6; i += 256) {
            int r = i / 6, u = i % 6;
            // global row stride = C_ bf16 = 48 uint4
            uint4 vh = qh[r * 48 + u];
            uint4 vl = ql[r * 48 + u];
            *(uint4*)(sm + SQH + r * (QSTRIDE * 2) + u * 16) = vh;
            *(uint4*)(sm + SQL + r * (QSTRIDE * 2) + u * 16) = vl;
        }
        const uint4* kh = (const uint4*)(g_kphi + (size_t)bh * LP * HD);
        const uint4* kl = (const uint4*)(g_kplo + (size_t)bh * LP * HD);
        for (int i = tid; i < LP * 6; i += 256) {
            int r = i / 6, u = i % 6;
            uint4 vh = kh[i];
            uint4 vl = kl[i];
            *(uint4*)(sm + SKH + r * (QSTRIDE * 2) + u * 16) = vh;
            *(uint4*)(sm + SKL + r * (QSTRIDE * 2) + u * 16) = vl;
        }
        // VPt rows are LP=288 bf16 = 576 B = 36 uint4 each  (R4 bug: used 18)
        const uint4* vh = (const uint4*)(g_vpthi + (size_t)bh * HD * LP);
        const uint4* vl = (const uint4*)(g_vptlo + (size_t)bh * HD * LP);
        for (int i = tid; i < HD * 36; i += 256) {
            int r = i / 36, u = i % 36;
            uint4 wh = vh[i];
            uint4 wl = vl[i];
            *(uint4*)(sm + SVH + r * (VSTRIDE * 2) + u * 16) = wh;
            *(uint4*)(sm + SVL + r * (VSTRIDE * 2) + u * 16) = wl;
        }
    }
    __syncthreads();

    const int aRow = (lane & 15);
    const int aKof = (lane >> 4) * 8;
    const int bRow = (lane & 7) + ((lane >> 3) & 1) * 8;
    const int bKof = (lane >> 4) * 8;

    // ---- Q fragments (held in registers across the whole loop) ----
    uint32_t qh[3][2][4], ql[3][2][4];
    #pragma unroll
    for (int ks = 0; ks < 3; ks++)
        #pragma unroll
        for (int mt = 0; mt < 2; mt++) {
            int so = (wid * 32 + mt * 16 + aRow) * (QSTRIDE * 2) + (ks * 16 + aKof) * 2;
            ldm_x4(qh[ks][mt], smem_u32(sm + SQH + so));
            ldm_x4(ql[ks][mt], smem_u32(sm + SQL + so));
        }

    float o[2][6][4];
    #pragma unroll
    for (int mt = 0; mt < 2; mt++)
        #pragma unroll
        for (int nt = 0; nt < 6; nt++)
            #pragma unroll
            for (int e = 0; e < 4; e++) o[mt][nt][e] = 0.f;
    float rs[2][2] = {{0.f, 0.f}, {0.f, 0.f}};

    for (int chunk = 0; chunk < 9; chunk++) {
        // ---- S = Q * KP^T over 32 L-columns ----
        float s[2][4][4];
        #pragma unroll
        for (int mt = 0; mt < 2; mt++)
            #pragma unroll
            for (int nt = 0; nt < 4; nt++)
                #pragma unroll
                for (int e = 0; e < 4; e++) s[mt][nt][e] = 0.f;

        #pragma unroll
        for (int ks = 0; ks < 3; ks++) {
            uint32_t kbh[4][2], kbl[4][2];
            #pragma unroll
            for (int np = 0; np < 2; np++) {
                int so = (chunk * 32 + np * 16 + bRow) * (QSTRIDE * 2)
                       + (ks * 16 + bKof) * 2;
                uint32_t t[4];
                ldm_x4(t, smem_u32(sm + SKH + so));
                kbh[np * 2    ][0] = t[0]; kbh[np * 2    ][1] = t[2];
                kbh[np * 2 + 1][0] = t[1]; kbh[np * 2 + 1][1] = t[3];
                ldm_x4(t, smem_u32(sm + SKL + so));
                kbl[np * 2    ][0] = t[0]; kbl[np * 2    ][1] = t[2];
                kbl[np * 2 + 1][0] = t[1]; kbl[np * 2 + 1][1] = t[3];
            }
            #pragma unroll
            for (int mt = 0; mt < 2; mt++)
                #pragma unroll
                for (int nt = 0; nt < 4; nt++) {
                    mma_bf16(s[mt][nt], qh[ks][mt], kbh[nt]);
                    mma_bf16(s[mt][nt], qh[ks][mt], kbl[nt]);
                    mma_bf16(s[mt][nt], ql[ks][mt], kbh[nt]);
                }
        }

        // ---- softmax numerator: e = 2^s, masked past L_, row sums ----
        #pragma unroll
        for (int mt = 0; mt < 2; mt++)
            #pragma unroll
            for (int nt = 0; nt < 4; nt++)
                #pragma unroll
                for (int e = 0; e < 4; e++) {
                    float v = ex2f(s[mt][nt][e]);
                    if (chunk == 8) {
                        int col = 256 + nt * 8 + (lane & 3) * 2 + (e & 1);
                        if (col >= L_) v = 0.f;
                    }
                    s[mt][nt][e] = v;
                    rs[mt][e >> 1] += v;
                }

        // ---- O += P * VP  (P from S-fragments, register-level repack) ----
        #pragma unroll
        for (int ks2 = 0; ks2 < 2; ks2++) {
            uint32_t ph[2][4], pl[2][4];
            #pragma unroll
            for (int mt = 0; mt < 2; mt++) {
                split_pack(s[mt][2 * ks2][0],     s[mt][2 * ks2][1],     ph[mt][0], pl[mt][0]);
                split_pack(s[mt][2 * ks2][2],     s[mt][2 * ks2][3],     ph[mt][1], pl[mt][1]);
                split_pack(s[mt][2 * ks2 + 1][0], s[mt][2 * ks2 + 1][1], ph[mt][2], pl[mt][2]);
                split_pack(s[mt][2 * ks2 + 1][2], s[mt][2 * ks2 + 1][3], ph[mt][3], pl[mt][3]);
            }
            uint32_t vbh[6][2], vbl[6][2];
            #pragma unroll
            for (int np = 0; np < 3; np++) {
                int so = (np * 16 + bRow) * (VSTRIDE * 2)
                       + (chunk * 32 + ks2 * 16 + bKof) * 2;
                uint32_t t[4];
                ldm_x4(t, smem_u32(sm + SVH + so));
                vbh[np * 2    ][0] = t[0]; vbh[np * 2    ][1] = t[2];
                vbh[np * 2 + 1][0] = t[1]; vbh[np * 2 + 1][1] = t[3];
                ldm_x4(t, smem_u32(sm + SVL + so));
                vbl[np * 2    ][0] = t[0]; vbl[np * 2    ][1] = t[2];
                vbl[np * 2 + 1][0] = t[1]; vbl[np * 2 + 1][1] = t[3];
            }
            #pragma unroll
            for (int mt = 0; mt < 2; mt++)
                #pragma unroll
                for (int nt = 0; nt < 6; nt++) {
                    mma_bf16(o[mt][nt], ph[mt], vbh[nt]);
                    mma_bf16(o[mt][nt], ph[mt], vbl[nt]);
                    mma_bf16(o[mt][nt], pl[mt], vbh[nt]);
                }
        }
    }

    // ---- finalize: reduce row sums across the 4 lanes of each row ----
    #pragma unroll
    for (int mt = 0; mt < 2; mt++)
        #pragma unroll
        for (int rhalf = 0; rhalf < 2; rhalf++) {
            float v = rs[mt][rhalf];
            v += __shfl_xor_sync(0xFFFFFFFF, v, 1);
            v += __shfl_xor_sync(0xFFFFFFFF, v, 2);
            rs[mt][rhalf] = 1.f / v;
        }

    // ---- write attention output as bf16 hi/lo for the projection GEMM ----
    #pragma unroll
    for (int mt = 0; mt < 2; mt++) {
        int rbase = n0 + wid * 32 + mt * 16 + (lane >> 2);
        #pragma unroll
        for (int nt = 0; nt < 6; nt++) {
            int cc = h * HD + nt * 8 + (lane & 3) * 2;
            uint32_t h0, l0, h1, l1;
            split_pack(o[mt][nt][0] * rs[mt][0], o[mt][nt][1] * rs[mt][0], h0, l0);
            split_pack(o[mt][nt][2] * rs[mt][1], o[mt][nt][3] * rs[mt][1], h1, l1);
            size_t r0o = (size_t)(b * NPIX + rbase) * C_ + cc;
            size_t r1o = (size_t)(b * NPIX + rbase + 8) * C_ + cc;
            *(uint32_t*)&g_aohi[r0o] = h0;
            *(uint32_t*)&g_aolo[r0o] = l0;
            *(uint32_t*)&g_aohi[r1o] = h1;
            *(uint32_t*)&g_aolo[r1o] = l1;
        }
    }
}

// ---------------------------------------------------------------------------
// Entry point
// ---------------------------------------------------------------------------
extern "C" void kernel_launch(void* const* d_in, const int* in_sizes, int n_in,
                              void* d_out, int out_size)
{
    const float* x      = (const float*)d_in[0];
    const float* w_qkv  = (const float*)d_in[1];
    const float* w_proj = (const float*)d_in[2];
    const float* b_proj = (const float*)d_in[3];
    float* out = (float*)d_out;

    cudaFuncSetAttribute(attn_mma_kernel,
                         cudaFuncAttributeMaxDynamicSharedMemorySize,
                         ATTN_SMEM);

    // 0) fp32 -> bf16 hi/lo conversions
    conv_x_kernel<<<(M_ * C_ / 4) / 256, 256>>>(x);
    conv_w_kernel<<<(QKN * C_ + C_ * C_ + 255) / 256, 256>>>(w_qkv, w_proj);

    // 1) QKV GEMM -> q (bf16 split, scaled), k/v (fp32)
    gemm_mma_kernel<<<dim3(QKN / 128, M_ / 128), 256>>>(nullptr, nullptr, 0);

    // 2) pyramid pooling + bf16 conversion
    pool16_kernel<<<dim3(256, B_ * NH), 64>>>();
    pool_rest_kernel<<<B_ * NH, 256>>>();
    conv_kv_kernel<<<B_ * NH, 256>>>();

    // 3) tensor-core attention (writes ao hi/lo bf16)
    attn_mma_kernel<<<dim3(NPIX / 256, B_ * NH), 256, ATTN_SMEM>>>();

    // 4) projection + bias -> d_out
    gemm_mma_kernel<<<dim3(C_ / 128, M_ / 128), 256>>>(out, b_proj, 1);
}

// round 6
// speedup vs baseline: 3.0713x; 1.4093x over previous
#include <cuda_runtime.h>
#include <cuda_bf16.h>
#include <cstdint>

// ---------------------------------------------------------------------------
// Problem constants
// ---------------------------------------------------------------------------
#define B_    8
#define NH    8
#define HD    48
#define HW    64
#define NPIX  4096            // 64*64
#define C_    384
#define M_    32768           // B_*NPIX
#define L_    277             // 1 + 4 + 16 + 256
#define LP    288             // padded L (9 chunks of 32)
#define QKN   1152            // 3*C_
#define MP_   (B_ * LP)       // 2304 pooled rows (padded)

// scale * log2(e) folded into q so logits are in log2 domain
#define QSC   0.2082351519f

// ---------------------------------------------------------------------------
// Scratch (allocation-free rule: __device__ globals)
// ---------------------------------------------------------------------------
__device__ float g_xp[MP_ * C_];               // pooled x, [b][lp][c]; pad rows stay 0

__device__ __nv_bfloat16 g_qhi[M_ * C_];       // q * QSC, split
__device__ __nv_bfloat16 g_qlo[M_ * C_];
__device__ __nv_bfloat16 g_xhi[M_ * C_];
__device__ __nv_bfloat16 g_xlo[M_ * C_];
__device__ __nv_bfloat16 g_xphi[MP_ * C_];     // pooled x, split
__device__ __nv_bfloat16 g_xplo[MP_ * C_];
__device__ __nv_bfloat16 g_wqT_hi[QKN * C_];   // w_qkv transposed: [1152, 384]
__device__ __nv_bfloat16 g_wqT_lo[QKN * C_];
__device__ __nv_bfloat16 g_wpT_hi[C_ * C_];    // w_proj transposed: [384, 384]
__device__ __nv_bfloat16 g_wpT_lo[C_ * C_];
__device__ __nv_bfloat16 g_aohi[M_ * C_];      // attention output, split
__device__ __nv_bfloat16 g_aolo[M_ * C_];

__device__ __nv_bfloat16 g_kphi[B_ * NH * LP * HD];   // [bh][l(288)][d]
__device__ __nv_bfloat16 g_kplo[B_ * NH * LP * HD];
__device__ __nv_bfloat16 g_vpthi[B_ * NH * HD * LP];  // [bh][d][l(288)]
__device__ __nv_bfloat16 g_vptlo[B_ * NH * HD * LP];

// ---------------------------------------------------------------------------
// Warp MMA helpers (sm_80+ PTX; no 'a'-suffix features)
// ---------------------------------------------------------------------------
__device__ __forceinline__ uint32_t smem_u32(const void* p) {
    uint32_t a;
    asm("{ .reg .u64 t; cvta.to.shared.u64 t, %1; cvt.u32.u64 %0, t; }"
        : "=r"(a) : "l"(p));
    return a;
}
__device__ __forceinline__ void ldm_x4(uint32_t* r, uint32_t addr) {
    asm volatile("ldmatrix.sync.aligned.m8n8.x4.shared.b16 {%0,%1,%2,%3}, [%4];"
        : "=r"(r[0]), "=r"(r[1]), "=r"(r[2]), "=r"(r[3]) : "r"(addr));
}
__device__ __forceinline__ void mma_bf16(float* c, const uint32_t* a,
                                         const uint32_t* b) {
    asm volatile(
        "mma.sync.aligned.m16n8k16.row.col.f32.bf16.bf16.f32 "
        "{%0,%1,%2,%3}, {%4,%5,%6,%7}, {%8,%9}, {%0,%1,%2,%3};"
        : "+f"(c[0]), "+f"(c[1]), "+f"(c[2]), "+f"(c[3])
        : "r"(a[0]), "r"(a[1]), "r"(a[2]), "r"(a[3]), "r"(b[0]), "r"(b[1]));
}
__device__ __forceinline__ float ex2f(float x) {
    float r;
    asm("ex2.approx.f32 %0, %1;" : "=f"(r) : "f"(x));
    return r;
}
__device__ __forceinline__ void split_pack(float a, float b,
                                           uint32_t& hi, uint32_t& lo) {
    __nv_bfloat162 h = __floats2bfloat162_rn(a, b);
    __nv_bfloat162 l = __floats2bfloat162_rn(a - __low2float(h),
                                             b - __high2float(h));
    hi = *(uint32_t*)&h;
    lo = *(uint32_t*)&l;
}

// ---------------------------------------------------------------------------
// Convert x (fp32) -> bf16 hi/lo
// ---------------------------------------------------------------------------
__global__ void conv_x_kernel(const float* __restrict__ x)
{
    int i = blockIdx.x * blockDim.x + threadIdx.x;          // per float4
    float4 v = ((const float4*)x)[i];
    uint32_t h0, l0, h1, l1;
    split_pack(v.x, v.y, h0, l0);
    split_pack(v.z, v.w, h1, l1);
    ((uint32_t*)g_xhi)[i * 2    ] = h0;
    ((uint32_t*)g_xhi)[i * 2 + 1] = h1;
    ((uint32_t*)g_xlo)[i * 2    ] = l0;
    ((uint32_t*)g_xlo)[i * 2 + 1] = l1;
}

// ---------------------------------------------------------------------------
// Convert pooled x (fp32) -> bf16 hi/lo (includes zero pad rows)
// ---------------------------------------------------------------------------
__global__ void conv_xp_kernel()
{
    int i = blockIdx.x * blockDim.x + threadIdx.x;          // per float4
    float4 v = ((const float4*)g_xp)[i];
    uint32_t h0, l0, h1, l1;
    split_pack(v.x, v.y, h0, l0);
    split_pack(v.z, v.w, h1, l1);
    ((uint32_t*)g_xphi)[i * 2    ] = h0;
    ((uint32_t*)g_xphi)[i * 2 + 1] = h1;
    ((uint32_t*)g_xplo)[i * 2    ] = l0;
    ((uint32_t*)g_xplo)[i * 2 + 1] = l1;
}

// ---------------------------------------------------------------------------
// Convert + transpose weights: w[K,N] -> wT[N,K] bf16 hi/lo
// ---------------------------------------------------------------------------
__global__ void conv_w_kernel(const float* __restrict__ wqkv,
                              const float* __restrict__ wp)
{
    int i = blockIdx.x * blockDim.x + threadIdx.x;
    const int NQ = QKN * C_;
    if (i < NQ) {
        int n = i / C_, k = i % C_;
        float v = wqkv[(size_t)k * QKN + n];
        __nv_bfloat16 h = __float2bfloat16(v);
        g_wqT_hi[i] = h;
        g_wqT_lo[i] = __float2bfloat16(v - __bfloat162float(h));
    } else {
        int j = i - NQ;
        if (j < C_ * C_) {
            int n = j / C_, k = j % C_;
            float v = wp[(size_t)k * C_ + n];
            __nv_bfloat16 h = __float2bfloat16(v);
            g_wpT_hi[j] = h;
            g_wpT_lo[j] = __float2bfloat16(v - __bfloat162float(h));
        }
    }
}

// ---------------------------------------------------------------------------
// Pool x directly (pooling commutes with the linear K/V projections).
// Stage 1: s=16 grid (4x4-pixel cells). grid (256 cells, 8 b), block 384 (=C).
// ---------------------------------------------------------------------------
__global__ void pool16_x_kernel(const float* __restrict__ x)
{
    const int c    = threadIdx.x;        // channel
    const int cell = blockIdx.x;         // ci*16 + cj
    const int b    = blockIdx.y;
    const int ci = cell >> 4, cj = cell & 15;

    float s = 0.f;
    #pragma unroll
    for (int dy = 0; dy < 4; dy++)
        #pragma unroll
        for (int dx = 0; dx < 4; dx++) {
            int n = (ci * 4 + dy) * HW + (cj * 4 + dx);
            s += x[(size_t)(b * NPIX + n) * C_ + c];
        }
    g_xp[(size_t)(b * LP + 21 + cell) * C_ + c] = s * (1.f / 16.f);
}

// ---------------------------------------------------------------------------
// Stage 2: derive s=4 (offset 5), s=2 (1), s=1 (0) hierarchically from s=16.
// One block per b, 384 threads.
// ---------------------------------------------------------------------------
__global__ void pool_rest_x_kernel()
{
    __shared__ float s4[16 * C_];
    __shared__ float s2[4 * C_];
    const int b   = blockIdx.x;
    const int tid = threadIdx.x;
    float* base = g_xp + (size_t)b * LP * C_;

    #pragma unroll
    for (int cell = 0; cell < 16; cell++) {
        int I = cell >> 2, J = cell & 3;
        float s = 0.f;
        #pragma unroll
        for (int di = 0; di < 4; di++)
            #pragma unroll
            for (int dj = 0; dj < 4; dj++)
                s += base[(21 + ((I * 4 + di) * 16 + (J * 4 + dj))) * C_ + tid];
        s *= (1.f / 16.f);
        s4[cell * C_ + tid] = s;
        base[(5 + cell) * C_ + tid] = s;
    }
    __syncthreads();

    #pragma unroll
    for (int cell = 0; cell < 4; cell++) {
        int I = cell >> 1, J = cell & 1;
        float s = 0.25f * (s4[((I * 2    ) * 4 + J * 2    ) * C_ + tid] +
                           s4[((I * 2    ) * 4 + J * 2 + 1) * C_ + tid] +
                           s4[((I * 2 + 1) * 4 + J * 2    ) * C_ + tid] +
                           s4[((I * 2 + 1) * 4 + J * 2 + 1) * C_ + tid]);
        s2[cell * C_ + tid] = s;
        base[(1 + cell) * C_ + tid] = s;
    }
    __syncthreads();

    base[tid] = 0.25f * (s2[tid] + s2[C_ + tid] + s2[2 * C_ + tid] + s2[3 * C_ + tid]);
}

// ---------------------------------------------------------------------------
// Tensor-core GEMM via mma.sync (bf16 3-term split, fp32 accumulate).
//   C = A[*,384] * B^T, B stored [N,384]
// Block 128x128, 8 warps (4x2), warp tile 32x64, BK = 32.
// mode 0: A = g_x (32768 rows), B = wqT cols 0..383     -> q bf16 split (scaled)
// mode 2: A = g_xp (2304 rows), B = wqT cols 384..1151  -> kp/vp scatter
// mode 1: A = g_ao (32768 rows), B = wpT                -> Cout + bias
// ---------------------------------------------------------------------------
#define ASTRIDE 40     // bf16 elems per SMEM row (32 data + 8 pad)

__global__ void __launch_bounds__(256) gemm_mma_kernel(
    float* __restrict__ Cout, const float* __restrict__ bias, int mode)
{
    __shared__ __nv_bfloat16 sAh[128 * ASTRIDE];
    __shared__ __nv_bfloat16 sAl[128 * ASTRIDE];
    __shared__ __nv_bfloat16 sBh[128 * ASTRIDE];
    __shared__ __nv_bfloat16 sBl[128 * ASTRIDE];

    const int tid  = threadIdx.x;
    const int lane = tid & 31;
    const int wid  = tid >> 5;
    const int wm   = wid & 3;
    const int wn   = wid >> 2;

    const __nv_bfloat16* Ahi = (mode == 0) ? g_xhi : (mode == 2) ? g_xphi : g_aohi;
    const __nv_bfloat16* Alo = (mode == 0) ? g_xlo : (mode == 2) ? g_xplo : g_aolo;
    const __nv_bfloat16* Bhi = (mode == 1) ? g_wpT_hi : g_wqT_hi;
    const __nv_bfloat16* Blo = (mode == 1) ? g_wpT_lo : g_wqT_lo;
    const int bcol0 = (mode == 2) ? C_ : 0;    // wqT row offset for k/v columns

    const int row0 = blockIdx.y * 128;
    const int col0 = blockIdx.x * 128;

    float acc[2][8][4];
    #pragma unroll
    for (int mt = 0; mt < 2; mt++)
        #pragma unroll
        for (int nt = 0; nt < 8; nt++)
            #pragma unroll
            for (int e = 0; e < 4; e++) acc[mt][nt][e] = 0.f;

    const int aRow = (lane & 15);
    const int aKof = (lane >> 4) * 8;
    const int bRow = (lane & 7) + ((lane >> 3) & 1) * 8;
    const int bKof = (lane >> 4) * 8;

    for (int c = 0; c < 12; c++) {
        const int koff = c * 32;
        #pragma unroll
        for (int j0 = 0; j0 < 2; j0++) {
            int j = tid * 2 + j0;
            int r = j >> 2, q = j & 3;
            size_t goA = (size_t)(row0 + r) * C_ + koff;
            size_t goB = (size_t)(bcol0 + col0 + r) * C_ + koff;
            uint4 vah = ((const uint4*)(Ahi + goA))[q];
            uint4 val = ((const uint4*)(Alo + goA))[q];
            uint4 vbh = ((const uint4*)(Bhi + goB))[q];
            uint4 vbl = ((const uint4*)(Blo + goB))[q];
            int so = r * ASTRIDE + q * 8;
            *(uint4*)&sAh[so] = vah;
            *(uint4*)&sAl[so] = val;
            *(uint4*)&sBh[so] = vbh;
            *(uint4*)&sBl[so] = vbl;
        }
        __syncthreads();

        #pragma unroll
        for (int ks = 0; ks < 2; ks++) {
            const int kk = ks * 16;
            uint32_t ah[2][4], al[2][4];
            #pragma unroll
            for (int mt = 0; mt < 2; mt++) {
                int so = (wm * 32 + mt * 16 + aRow) * ASTRIDE + kk + aKof;
                ldm_x4(ah[mt], smem_u32(&sAh[so]));
                ldm_x4(al[mt], smem_u32(&sAl[so]));
            }
            uint32_t bh[8][2], bl[8][2];
            #pragma unroll
            for (int np = 0; np < 4; np++) {
                int so = (wn * 64 + np * 16 + bRow) * ASTRIDE + kk + bKof;
                uint32_t t[4];
                ldm_x4(t, smem_u32(&sBh[so]));
                bh[np * 2    ][0] = t[0]; bh[np * 2    ][1] = t[2];
                bh[np * 2 + 1][0] = t[1]; bh[np * 2 + 1][1] = t[3];
                ldm_x4(t, smem_u32(&sBl[so]));
                bl[np * 2    ][0] = t[0]; bl[np * 2    ][1] = t[2];
                bl[np * 2 + 1][0] = t[1]; bl[np * 2 + 1][1] = t[3];
            }
            #pragma unroll
            for (int mt = 0; mt < 2; mt++)
                #pragma unroll
                for (int nt = 0; nt < 8; nt++) {
                    mma_bf16(acc[mt][nt], ah[mt], bh[nt]);
                    mma_bf16(acc[mt][nt], ah[mt], bl[nt]);
                    mma_bf16(acc[mt][nt], al[mt], bh[nt]);
                }
        }
        __syncthreads();
    }

    // ---- epilogue ----
    const int mrow = row0 + wm * 32 + (lane >> 2);
    const int ncol = wn * 64 + (lane & 3) * 2;

    if (mode == 0) {
        // q: scale, split to bf16 hi/lo
        #pragma unroll
        for (int mt = 0; mt < 2; mt++)
            #pragma unroll
            for (int nt = 0; nt < 8; nt++) {
                int r  = mrow + mt * 16;
                int cc = col0 + ncol + nt * 8;
                uint32_t h0, l0, h1, l1;
                split_pack(acc[mt][nt][0] * QSC, acc[mt][nt][1] * QSC, h0, l0);
                split_pack(acc[mt][nt][2] * QSC, acc[mt][nt][3] * QSC, h1, l1);
                *(uint32_t*)&g_qhi[(size_t)r * C_ + cc]       = h0;
                *(uint32_t*)&g_qlo[(size_t)r * C_ + cc]       = l0;
                *(uint32_t*)&g_qhi[(size_t)(r + 8) * C_ + cc] = h1;
                *(uint32_t*)&g_qlo[(size_t)(r + 8) * C_ + cc] = l1;
            }
        return;
    }

    if (mode == 2) {
        // kp/vp scatter: row = b*288 + l; col picks k-vs-v, head, dim
        #pragma unroll
        for (int mt = 0; mt < 2; mt++)
            #pragma unroll
            for (int nt = 0; nt < 8; nt++) {
                int gc = col0 + ncol + nt * 8;       // 0..767
                int t  = gc / C_;                    // 0 -> kp, 1 -> vp
                int cc = gc - t * C_;
                int hh = cc / HD, d = cc % HD;       // d is even
                #pragma unroll
                for (int half = 0; half < 2; half++) {
                    int r = mrow + mt * 16 + half * 8;
                    int b = r / LP, l = r % LP;
                    float a0 = acc[mt][nt][half * 2 + 0];
                    float a1 = acc[mt][nt][half * 2 + 1];
                    if (t == 0) {
                        uint32_t hi, lo;
                        split_pack(a0, a1, hi, lo);
                        size_t o = ((size_t)(b * NH + hh) * LP + l) * HD + d;
                        *(uint32_t*)&g_kphi[o] = hi;
                        *(uint32_t*)&g_kplo[o] = lo;
                    } else {
                        __nv_bfloat16 b0 = __float2bfloat16(a0);
                        __nv_bfloat16 b1 = __float2bfloat16(a1);
                        size_t o0 = ((size_t)(b * NH + hh) * HD + d)     * LP + l;
                        size_t o1 = ((size_t)(b * NH + hh) * HD + d + 1) * LP + l;
                        g_vpthi[o0] = b0;
                        g_vptlo[o0] = __float2bfloat16(a0 - __bfloat162float(b0));
                        g_vpthi[o1] = b1;
                        g_vptlo[o1] = __float2bfloat16(a1 - __bfloat162float(b1));
                    }
                }
            }
        return;
    }

    // mode 1: projection output + bias
    #pragma unroll
    for (int mt = 0; mt < 2; mt++)
        #pragma unroll
        for (int nt = 0; nt < 8; nt++) {
            int r  = mrow + mt * 16;
            int cc = col0 + ncol + nt * 8;
            float2 v0 = make_float2(acc[mt][nt][0] + bias[cc],
                                    acc[mt][nt][1] + bias[cc + 1]);
            float2 v1 = make_float2(acc[mt][nt][2] + bias[cc],
                                    acc[mt][nt][3] + bias[cc + 1]);
            *(float2*)&Cout[(size_t)r * C_ + cc]       = v0;
            *(float2*)&Cout[(size_t)(r + 8) * C_ + cc] = v1;
        }
}

// ---------------------------------------------------------------------------
// Tensor-core attention. One CTA = one (b,h) x 256 q rows; 8 warps x 32 rows.
// KP [l][d] and VPt [d][l] staged in SMEM as bf16 hi/lo; Q frags in registers.
// No-max softmax in log2 domain (scale*log2e pre-folded into q).
// ---------------------------------------------------------------------------
#define QSTRIDE 56          // 48 + 8 pad  (conflict-free ldmatrix)
#define VSTRIDE 296         // 288 + 8 pad

#define SQH 0
#define SQL (SQH + 256 * QSTRIDE * 2)
#define SKH (SQL + 256 * QSTRIDE * 2)
#define SKL (SKH + LP * QSTRIDE * 2)
#define SVH (SKL + LP * QSTRIDE * 2)
#define SVL (SVH + HD * VSTRIDE * 2)
#define ATTN_SMEM (SVL + HD * VSTRIDE * 2)    // 178688 B

__global__ void __launch_bounds__(256, 1) attn_mma_kernel()
{
    extern __shared__ char sm[];

    const int tid  = threadIdx.x;
    const int lane = tid & 31;
    const int wid  = tid >> 5;
    const int bh   = blockIdx.y;
    const int b    = bh >> 3, h = bh & 7;
    const int n0   = blockIdx.x * 256;

    // ---- prologue: stage Q, KP, VPt into SMEM ----
    {
        const uint4* qh = (const uint4*)(g_qhi + (size_t)(b * NPIX + n0) * C_ + h * HD);
        const uint4* ql = (const uint4*)(g_qlo + (size_t)(b * NPIX + n0) * C_ + h * HD);
        for (int i = tid; i < 256 * 6; i += 256) {
            int r = i / 6, u = i % 6;
            uint4 vh = qh[r * 48 + u];
            uint4 vl = ql[r * 48 + u];
            *(uint4*)(sm + SQH + r * (QSTRIDE * 2) + u * 16) = vh;
            *(uint4*)(sm + SQL + r * (QSTRIDE * 2) + u * 16) = vl;
        }
        const uint4* kh = (const uint4*)(g_kphi + (size_t)bh * LP * HD);
        const uint4* kl = (const uint4*)(g_kplo + (size_t)bh * LP * HD);
        for (int i = tid; i < LP * 6; i += 256) {
            int r = i / 6, u = i % 6;
            uint4 vh = kh[i];
            uint4 vl = kl[i];
            *(uint4*)(sm + SKH + r * (QSTRIDE * 2) + u * 16) = vh;
            *(uint4*)(sm + SKL + r * (QSTRIDE * 2) + u * 16) = vl;
        }
        const uint4* vh = (const uint4*)(g_vpthi + (size_t)bh * HD * LP);
        const uint4* vl = (const uint4*)(g_vptlo + (size_t)bh * HD * LP);
        for (int i = tid; i < HD * 36; i += 256) {
            int r = i / 36, u = i % 36;
            uint4 wh = vh[i];
            uint4 wl = vl[i];
            *(uint4*)(sm + SVH + r * (VSTRIDE * 2) + u * 16) = wh;
            *(uint4*)(sm + SVL + r * (VSTRIDE * 2) + u * 16) = wl;
        }
    }
    __syncthreads();

    const int aRow = (lane & 15);
    const int aKof = (lane >> 4) * 8;
    const int bRow = (lane & 7) + ((lane >> 3) & 1) * 8;
    const int bKof = (lane >> 4) * 8;

    // ---- Q fragments (held in registers across the whole loop) ----
    uint32_t qh[3][2][4], ql[3][2][4];
    #pragma unroll
    for (int ks = 0; ks < 3; ks++)
        #pragma unroll
        for (int mt = 0; mt < 2; mt++) {
            int so = (wid * 32 + mt * 16 + aRow) * (QSTRIDE * 2) + (ks * 16 + aKof) * 2;
            ldm_x4(qh[ks][mt], smem_u32(sm + SQH + so));
            ldm_x4(ql[ks][mt], smem_u32(sm + SQL + so));
        }

    float o[2][6][4];
    #pragma unroll
    for (int mt = 0; mt < 2; mt++)
        #pragma unroll
        for (int nt = 0; nt < 6; nt++)
            #pragma unroll
            for (int e = 0; e < 4; e++) o[mt][nt][e] = 0.f;
    float rs[2][2] = {{0.f, 0.f}, {0.f, 0.f}};

    for (int chunk = 0; chunk < 9; chunk++) {
        // ---- S = Q * KP^T over 32 L-columns ----
        float s[2][4][4];
        #pragma unroll
        for (int mt = 0; mt < 2; mt++)
            #pragma unroll
            for (int nt = 0; nt < 4; nt++)
                #pragma unroll
                for (int e = 0; e < 4; e++) s[mt][nt][e] = 0.f;

        #pragma unroll
        for (int ks = 0; ks < 3; ks++) {
            uint32_t kbh[4][2], kbl[4][2];
            #pragma unroll
            for (int np = 0; np < 2; np++) {
                int so = (chunk * 32 + np * 16 + bRow) * (QSTRIDE * 2)
                       + (ks * 16 + bKof) * 2;
                uint32_t t[4];
                ldm_x4(t, smem_u32(sm + SKH + so));
                kbh[np * 2    ][0] = t[0]; kbh[np * 2    ][1] = t[2];
                kbh[np * 2 + 1][0] = t[1]; kbh[np * 2 + 1][1] = t[3];
                ldm_x4(t, smem_u32(sm + SKL + so));
                kbl[np * 2    ][0] = t[0]; kbl[np * 2    ][1] = t[2];
                kbl[np * 2 + 1][0] = t[1]; kbl[np * 2 + 1][1] = t[3];
            }
            #pragma unroll
            for (int mt = 0; mt < 2; mt++)
                #pragma unroll
                for (int nt = 0; nt < 4; nt++) {
                    mma_bf16(s[mt][nt], qh[ks][mt], kbh[nt]);
                    mma_bf16(s[mt][nt], qh[ks][mt], kbl[nt]);
                    mma_bf16(s[mt][nt], ql[ks][mt], kbh[nt]);
                }
        }

        // ---- softmax numerator: e = 2^s, masked past L_, row sums ----
        #pragma unroll
        for (int mt = 0; mt < 2; mt++)
            #pragma unroll
            for (int nt = 0; nt < 4; nt++)
                #pragma unroll
                for (int e = 0; e < 4; e++) {
                    float v = ex2f(s[mt][nt][e]);
                    if (chunk == 8) {
                        int col = 256 + nt * 8 + (lane & 3) * 2 + (e & 1);
                        if (col >= L_) v = 0.f;
                    }
                    s[mt][nt][e] = v;
                    rs[mt][e >> 1] += v;
                }

        // ---- O += P * VP  (P from S-fragments, register-level repack) ----
        #pragma unroll
        for (int ks2 = 0; ks2 < 2; ks2++) {
            uint32_t ph[2][4], pl[2][4];
            #pragma unroll
            for (int mt = 0; mt < 2; mt++) {
                split_pack(s[mt][2 * ks2][0],     s[mt][2 * ks2][1],     ph[mt][0], pl[mt][0]);
                split_pack(s[mt][2 * ks2][2],     s[mt][2 * ks2][3],     ph[mt][1], pl[mt][1]);
                split_pack(s[mt][2 * ks2 + 1][0], s[mt][2 * ks2 + 1][1], ph[mt][2], pl[mt][2]);
                split_pack(s[mt][2 * ks2 + 1][2], s[mt][2 * ks2 + 1][3], ph[mt][3], pl[mt][3]);
            }
            uint32_t vbh[6][2], vbl[6][2];
            #pragma unroll
            for (int np = 0; np < 3; np++) {
                int so = (np * 16 + bRow) * (VSTRIDE * 2)
                       + (chunk * 32 + ks2 * 16 + bKof) * 2;
                uint32_t t[4];
                ldm_x4(t, smem_u32(sm + SVH + so));
                vbh[np * 2    ][0] = t[0]; vbh[np * 2    ][1] = t[2];
                vbh[np * 2 + 1][0] = t[1]; vbh[np * 2 + 1][1] = t[3];
                ldm_x4(t, smem_u32(sm + SVL + so));
                vbl[np * 2    ][0] = t[0]; vbl[np * 2    ][1] = t[2];
                vbl[np * 2 + 1][0] = t[1]; vbl[np * 2 + 1][1] = t[3];
            }
            #pragma unroll
            for (int mt = 0; mt < 2; mt++)
                #pragma unroll
                for (int nt = 0; nt < 6; nt++) {
                    mma_bf16(o[mt][nt], ph[mt], vbh[nt]);
                    mma_bf16(o[mt][nt], ph[mt], vbl[nt]);
                    mma_bf16(o[mt][nt], pl[mt], vbh[nt]);
                }
        }
    }

    // ---- finalize: reduce row sums across the 4 lanes of each row ----
    #pragma unroll
    for (int mt = 0; mt < 2; mt++)
        #pragma unroll
        for (int rhalf = 0; rhalf < 2; rhalf++) {
            float v = rs[mt][rhalf];
            v += __shfl_xor_sync(0xFFFFFFFF, v, 1);
            v += __shfl_xor_sync(0xFFFFFFFF, v, 2);
            rs[mt][rhalf] = 1.f / v;
        }

    // ---- write attention output as bf16 hi/lo for the projection GEMM ----
    #pragma unroll
    for (int mt = 0; mt < 2; mt++) {
        int rbase = n0 + wid * 32 + mt * 16 + (lane >> 2);
        #pragma unroll
        for (int nt = 0; nt < 6; nt++) {
            int cc = h * HD + nt * 8 + (lane & 3) * 2;
            uint32_t h0, l0, h1, l1;
            split_pack(o[mt][nt][0] * rs[mt][0], o[mt][nt][1] * rs[mt][0], h0, l0);
            split_pack(o[mt][nt][2] * rs[mt][1], o[mt][nt][3] * rs[mt][1], h1, l1);
            size_t r0o = (size_t)(b * NPIX + rbase) * C_ + cc;
            size_t r1o = (size_t)(b * NPIX + rbase + 8) * C_ + cc;
            *(uint32_t*)&g_aohi[r0o] = h0;
            *(uint32_t*)&g_aolo[r0o] = l0;
            *(uint32_t*)&g_aohi[r1o] = h1;
            *(uint32_t*)&g_aolo[r1o] = l1;
        }
    }
}

// ---------------------------------------------------------------------------
// Entry point
// ---------------------------------------------------------------------------
extern "C" void kernel_launch(void* const* d_in, const int* in_sizes, int n_in,
                              void* d_out, int out_size)
{
    const float* x      = (const float*)d_in[0];
    const float* w_qkv  = (const float*)d_in[1];
    const float* w_proj = (const float*)d_in[2];
    const float* b_proj = (const float*)d_in[3];
    float* out = (float*)d_out;

    cudaFuncSetAttribute(attn_mma_kernel,
                         cudaFuncAttributeMaxDynamicSharedMemorySize,
                         ATTN_SMEM);

    // 0) conversions + x pooling (pooling commutes with K/V projection)
    conv_x_kernel<<<(M_ * C_ / 4) / 256, 256>>>(x);
    conv_w_kernel<<<(QKN * C_ + C_ * C_ + 255) / 256, 256>>>(w_qkv, w_proj);
    pool16_x_kernel<<<dim3(256, B_), C_>>>(x);
    pool_rest_x_kernel<<<B_, C_>>>();
    conv_xp_kernel<<<(MP_ * C_ / 4) / 256, 256>>>();

    // 1) Q GEMM (32768 x 384 x 384) -> q bf16 split, scaled
    gemm_mma_kernel<<<dim3(3, M_ / 128), 256>>>(nullptr, nullptr, 0);

    // 2) K/V GEMM on pooled rows (2304 x 768 x 384) -> kp / vp (transposed)
    gemm_mma_kernel<<<dim3(6, MP_ / 128), 256>>>(nullptr, nullptr, 2);

    // 3) tensor-core attention (writes ao hi/lo bf16)
    attn_mma_kernel<<<dim3(NPIX / 256, B_ * NH), 256, ATTN_SMEM>>>();

    // 4) projection + bias -> d_out
    gemm_mma_kernel<<<dim3(3, M_ / 128), 256>>>(out, b_proj, 1);
}

// round 7
// speedup vs baseline: 3.4801x; 1.1331x over previous
#include <cuda_runtime.h>
#include <cuda_bf16.h>
#include <cstdint>

// ---------------------------------------------------------------------------
// Problem constants
// ---------------------------------------------------------------------------
#define B_    8
#define NH    8
#define HD    48
#define HW    64
#define NPIX  4096            // 64*64
#define C_    384
#define M_    32768           // B_*NPIX
#define L_    277             // 1 + 4 + 16 + 256
#define LP    288             // padded L (9 chunks of 32)
#define QKN   1152            // 3*C_
#define MP_   (B_ * LP)       // 2304 pooled rows (padded)

// scale * log2(e) folded into q so logits are in log2 domain
#define QSC   0.2082351519f

// ---------------------------------------------------------------------------
// Scratch (allocation-free rule: __device__ globals; zero-initialized)
// ---------------------------------------------------------------------------
__device__ float g_xp[MP_ * C_];               // pooled x, [b][lp][c]; pad rows stay 0

__device__ __nv_bfloat16 g_qhi[M_ * C_];       // q * QSC, split
__device__ __nv_bfloat16 g_qlo[M_ * C_];
__device__ __nv_bfloat16 g_xhi[M_ * C_];
__device__ __nv_bfloat16 g_xlo[M_ * C_];
__device__ __nv_bfloat16 g_xphi[MP_ * C_];     // pooled x, split
__device__ __nv_bfloat16 g_xplo[MP_ * C_];
__device__ __nv_bfloat16 g_wqT_hi[QKN * C_];   // w_qkv transposed: [1152, 384]
__device__ __nv_bfloat16 g_wqT_lo[QKN * C_];
__device__ __nv_bfloat16 g_wpT_hi[C_ * C_];    // w_proj transposed: [384, 384]
__device__ __nv_bfloat16 g_wpT_lo[C_ * C_];
__device__ __nv_bfloat16 g_aohi[M_ * C_];      // attention output, split
__device__ __nv_bfloat16 g_aolo[M_ * C_];

__device__ __nv_bfloat16 g_kphi[B_ * NH * LP * HD];   // [bh][l(288)][d]
__device__ __nv_bfloat16 g_kplo[B_ * NH * LP * HD];
__device__ __nv_bfloat16 g_vpthi[B_ * NH * HD * LP];  // [bh][d][l(288)]
__device__ __nv_bfloat16 g_vptlo[B_ * NH * HD * LP];

// ---------------------------------------------------------------------------
// PTX helpers (sm_80+ only; no 'a'-suffix features)
// ---------------------------------------------------------------------------
__device__ __forceinline__ uint32_t smem_u32(const void* p) {
    uint32_t a;
    asm("{ .reg .u64 t; cvta.to.shared.u64 t, %1; cvt.u32.u64 %0, t; }"
        : "=r"(a) : "l"(p));
    return a;
}
__device__ __forceinline__ void ldm_x4(uint32_t* r, uint32_t addr) {
    asm volatile("ldmatrix.sync.aligned.m8n8.x4.shared.b16 {%0,%1,%2,%3}, [%4];"
        : "=r"(r[0]), "=r"(r[1]), "=r"(r[2]), "=r"(r[3]) : "r"(addr));
}
__device__ __forceinline__ void mma_bf16(float* c, const uint32_t* a,
                                         const uint32_t* b) {
    asm volatile(
        "mma.sync.aligned.m16n8k16.row.col.f32.bf16.bf16.f32 "
        "{%0,%1,%2,%3}, {%4,%5,%6,%7}, {%8,%9}, {%0,%1,%2,%3};"
        : "+f"(c[0]), "+f"(c[1]), "+f"(c[2]), "+f"(c[3])
        : "r"(a[0]), "r"(a[1]), "r"(a[2]), "r"(a[3]), "r"(b[0]), "r"(b[1]));
}
__device__ __forceinline__ float ex2f(float x) {
    float r;
    asm("ex2.approx.f32 %0, %1;" : "=f"(r) : "f"(x));
    return r;
}
__device__ __forceinline__ void split_pack(float a, float b,
                                           uint32_t& hi, uint32_t& lo) {
    __nv_bfloat162 h = __floats2bfloat162_rn(a, b);
    __nv_bfloat162 l = __floats2bfloat162_rn(a - __low2float(h),
                                             b - __high2float(h));
    hi = *(uint32_t*)&h;
    lo = *(uint32_t*)&l;
}
#define CP16(dst, src) \
    asm volatile("cp.async.cg.shared.global [%0], [%1], 16;" \
                 :: "r"(dst), "l"(src))
#define CP_COMMIT()  asm volatile("cp.async.commit_group;" ::: "memory")
#define CP_WAIT0()   asm volatile("cp.async.wait_group 0;" ::: "memory")

// ---------------------------------------------------------------------------
// Fused: x -> bf16 hi/lo conversion  +  s=16 pooling (cells partition pixels).
// grid (256 cells, 8 b), block 192: thread = channel pair (2c, 2c+1).
// ---------------------------------------------------------------------------
__global__ void conv_pool16_kernel(const float* __restrict__ x)
{
    const int c    = threadIdx.x * 2;
    const int cell = blockIdx.x;
    const int b    = blockIdx.y;
    const int ci = cell >> 4, cj = cell & 15;

    float s0 = 0.f, s1 = 0.f;
    #pragma unroll
    for (int dy = 0; dy < 4; dy++)
        #pragma unroll
        for (int dx = 0; dx < 4; dx++) {
            int n = (ci * 4 + dy) * HW + (cj * 4 + dx);
            size_t e = (size_t)(b * NPIX + n) * C_ + c;
            float2 v = *(const float2*)&x[e];
            uint32_t hi, lo;
            split_pack(v.x, v.y, hi, lo);
            ((uint32_t*)g_xhi)[e >> 1] = hi;
            ((uint32_t*)g_xlo)[e >> 1] = lo;
            s0 += v.x; s1 += v.y;
        }
    float2 o = make_float2(s0 * (1.f / 16.f), s1 * (1.f / 16.f));
    *(float2*)&g_xp[(size_t)(b * LP + 21 + cell) * C_ + c] = o;
}

// ---------------------------------------------------------------------------
// s=4 cells from s=16 (exact: mean of equal-size means). grid (16, 8), blk 384.
// ---------------------------------------------------------------------------
__global__ void pool4_x_kernel()
{
    const int cell = blockIdx.x;
    const int b    = blockIdx.y;
    const int c    = threadIdx.x;
    const int I = cell >> 2, J = cell & 3;
    float* base = g_xp + (size_t)b * LP * C_;

    float s = 0.f;
    #pragma unroll
    for (int di = 0; di < 4; di++)
        #pragma unroll
        for (int dj = 0; dj < 4; dj++)
            s += base[(21 + ((I * 4 + di) * 16 + (J * 4 + dj))) * C_ + c];
    base[(5 + cell) * C_ + c] = s * (1.f / 16.f);
}

// ---------------------------------------------------------------------------
// s=2 and s=1 from s=4. grid 8, block 384.
// ---------------------------------------------------------------------------
__global__ void pool21_x_kernel()
{
    const int b = blockIdx.x;
    const int c = threadIdx.x;
    float* base = g_xp + (size_t)b * LP * C_;

    float s4v[16];
    #pragma unroll
    for (int i = 0; i < 16; i++) s4v[i] = base[(5 + i) * C_ + c];

    float s2v[4];
    #pragma unroll
    for (int cell = 0; cell < 4; cell++) {
        int I = cell >> 1, J = cell & 1;
        float s = 0.25f * (s4v[(I * 2    ) * 4 + J * 2    ] +
                           s4v[(I * 2    ) * 4 + J * 2 + 1] +
                           s4v[(I * 2 + 1) * 4 + J * 2    ] +
                           s4v[(I * 2 + 1) * 4 + J * 2 + 1]);
        s2v[cell] = s;
        base[(1 + cell) * C_ + c] = s;
    }
    base[c] = 0.25f * (s2v[0] + s2v[1] + s2v[2] + s2v[3]);
}

// ---------------------------------------------------------------------------
// Convert pooled x (fp32) -> bf16 hi/lo (includes zero pad rows)
// ---------------------------------------------------------------------------
__global__ void conv_xp_kernel()
{
    int i = blockIdx.x * blockDim.x + threadIdx.x;          // per float4
    float4 v = ((const float4*)g_xp)[i];
    uint32_t h0, l0, h1, l1;
    split_pack(v.x, v.y, h0, l0);
    split_pack(v.z, v.w, h1, l1);
    ((uint32_t*)g_xphi)[i * 2    ] = h0;
    ((uint32_t*)g_xphi)[i * 2 + 1] = h1;
    ((uint32_t*)g_xplo)[i * 2    ] = l0;
    ((uint32_t*)g_xplo)[i * 2 + 1] = l1;
}

// ---------------------------------------------------------------------------
// Convert + transpose weights: w[K,N] -> wT[N,K] bf16 hi/lo
// ---------------------------------------------------------------------------
__global__ void conv_w_kernel(const float* __restrict__ wqkv,
                              const float* __restrict__ wp)
{
    int i = blockIdx.x * blockDim.x + threadIdx.x;
    const int NQ = QKN * C_;
    if (i < NQ) {
        int n = i / C_, k = i % C_;
        float v = wqkv[(size_t)k * QKN + n];
        __nv_bfloat16 h = __float2bfloat16(v);
        g_wqT_hi[i] = h;
        g_wqT_lo[i] = __float2bfloat16(v - __bfloat162float(h));
    } else {
        int j = i - NQ;
        if (j < C_ * C_) {
            int n = j / C_, k = j % C_;
            float v = wp[(size_t)k * C_ + n];
            __nv_bfloat16 h = __float2bfloat16(v);
            g_wpT_hi[j] = h;
            g_wpT_lo[j] = __float2bfloat16(v - __bfloat162float(h));
        }
    }
}

// ---------------------------------------------------------------------------
// Tensor-core GEMM, cp.async 2-stage double-buffered.
//   C = A[*,384] * B^T, B stored [N,384]
// Block 128x128, 8 warps (4x2), warp tile 32x64, BK = 32, 12 K-chunks.
// mode 0: A = g_x (32768 rows), B = wqT cols 0..383     -> q bf16 split (scaled)
// mode 2: A = g_xp (2304 rows), B = wqT cols 384..1151  -> kp/vp scatter
// mode 1: A = g_ao (32768 rows), B = wpT                -> Cout + bias
// ---------------------------------------------------------------------------
#define ASTRIDE 40         // bf16 elems per SMEM row (32 data + 8 pad) = 80 B
#define TILE_B  10240      // one 128-row tile, bytes
#define GSTG    (4 * TILE_B)      // Ah, Al, Bh, Bl per stage
#define GEMM_SMEM (2 * GSTG)      // 81920 B

__global__ void __launch_bounds__(256) gemm_mma_kernel(
    float* __restrict__ Cout, const float* __restrict__ bias, int mode)
{
    extern __shared__ char gsm[];

    const int tid  = threadIdx.x;
    const int lane = tid & 31;
    const int wid  = tid >> 5;
    const int wm   = wid & 3;
    const int wn   = wid >> 2;

    const __nv_bfloat16* Ahi = (mode == 0) ? g_xhi : (mode == 2) ? g_xphi : g_aohi;
    const __nv_bfloat16* Alo = (mode == 0) ? g_xlo : (mode == 2) ? g_xplo : g_aolo;
    const __nv_bfloat16* Bhi = (mode == 1) ? g_wpT_hi : g_wqT_hi;
    const __nv_bfloat16* Blo = (mode == 1) ? g_wpT_lo : g_wqT_lo;
    const int bcol0 = (mode == 2) ? C_ : 0;    // wqT row offset for k/v columns

    const int row0 = blockIdx.y * 128;
    const int col0 = blockIdx.x * 128;

    // per-thread cp.async slots: two 16B per array per chunk
    const int r0 = (tid * 2)     >> 2, q0 = (tid * 2)     & 3;
    const int r1 = (tid * 2 + 1) >> 2, q1 = (tid * 2 + 1) & 3;

    auto issue_chunk = [&](int c, int stg) {
        const int koff = c * 32;
        char* sb = gsm + stg * GSTG;
        {
            size_t gA = (size_t)(row0 + r0) * C_ + koff + q0 * 8;
            size_t gB = (size_t)(bcol0 + col0 + r0) * C_ + koff + q0 * 8;
            uint32_t so = smem_u32(sb) + r0 * 80 + q0 * 16;
            CP16(so,              Ahi + gA);
            CP16(so + TILE_B,     Alo + gA);
            CP16(so + 2 * TILE_B, Bhi + gB);
            CP16(so + 3 * TILE_B, Blo + gB);
        }
        {
            size_t gA = (size_t)(row0 + r1) * C_ + koff + q1 * 8;
            size_t gB = (size_t)(bcol0 + col0 + r1) * C_ + koff + q1 * 8;
            uint32_t so = smem_u32(sb) + r1 * 80 + q1 * 16;
            CP16(so,              Ahi + gA);
            CP16(so + TILE_B,     Alo + gA);
            CP16(so + 2 * TILE_B, Bhi + gB);
            CP16(so + 3 * TILE_B, Blo + gB);
        }
        CP_COMMIT();
    };

    float acc[2][8][4];
    #pragma unroll
    for (int mt = 0; mt < 2; mt++)
        #pragma unroll
        for (int nt = 0; nt < 8; nt++)
            #pragma unroll
            for (int e = 0; e < 4; e++) acc[mt][nt][e] = 0.f;

    const int aRow = (lane & 15);
    const int aKof = (lane >> 4) * 8;
    const int bRow = (lane & 7) + ((lane >> 3) & 1) * 8;
    const int bKof = (lane >> 4) * 8;

    issue_chunk(0, 0);

    for (int c = 0; c < 12; c++) {
        CP_WAIT0();
        __syncthreads();
        if (c + 1 < 12) issue_chunk(c + 1, (c + 1) & 1);

        char* sb = gsm + (c & 1) * GSTG;
        const uint32_t sA  = smem_u32(sb);
        const uint32_t sB  = sA + 2 * TILE_B;

        #pragma unroll
        for (int ks = 0; ks < 2; ks++) {
            const int kk = ks * 16;
            uint32_t ah[2][4], al[2][4];
            #pragma unroll
            for (int mt = 0; mt < 2; mt++) {
                uint32_t so = (wm * 32 + mt * 16 + aRow) * 80 + (kk + aKof) * 2;
                ldm_x4(ah[mt], sA + so);
                ldm_x4(al[mt], sA + TILE_B + so);
            }
            uint32_t bh[8][2], bl[8][2];
            #pragma unroll
            for (int np = 0; np < 4; np++) {
                uint32_t so = (wn * 64 + np * 16 + bRow) * 80 + (kk + bKof) * 2;
                uint32_t t[4];
                ldm_x4(t, sB + so);
                bh[np * 2    ][0] = t[0]; bh[np * 2    ][1] = t[2];
                bh[np * 2 + 1][0] = t[1]; bh[np * 2 + 1][1] = t[3];
                ldm_x4(t, sB + TILE_B + so);
                bl[np * 2    ][0] = t[0]; bl[np * 2    ][1] = t[2];
                bl[np * 2 + 1][0] = t[1]; bl[np * 2 + 1][1] = t[3];
            }
            #pragma unroll
            for (int mt = 0; mt < 2; mt++)
                #pragma unroll
                for (int nt = 0; nt < 8; nt++) {
                    mma_bf16(acc[mt][nt], ah[mt], bh[nt]);
                    mma_bf16(acc[mt][nt], ah[mt], bl[nt]);
                    mma_bf16(acc[mt][nt], al[mt], bh[nt]);
                }
        }
    }

    // ---- epilogue ----
    const int mrow = row0 + wm * 32 + (lane >> 2);
    const int ncol = wn * 64 + (lane & 3) * 2;

    if (mode == 0) {
        // q: scale, split to bf16 hi/lo
        #pragma unroll
        for (int mt = 0; mt < 2; mt++)
            #pragma unroll
            for (int nt = 0; nt < 8; nt++) {
                int r  = mrow + mt * 16;
                int cc = col0 + ncol + nt * 8;
                uint32_t h0, l0, h1, l1;
                split_pack(acc[mt][nt][0] * QSC, acc[mt][nt][1] * QSC, h0, l0);
                split_pack(acc[mt][nt][2] * QSC, acc[mt][nt][3] * QSC, h1, l1);
                *(uint32_t*)&g_qhi[(size_t)r * C_ + cc]       = h0;
                *(uint32_t*)&g_qlo[(size_t)r * C_ + cc]       = l0;
                *(uint32_t*)&g_qhi[(size_t)(r + 8) * C_ + cc] = h1;
                *(uint32_t*)&g_qlo[(size_t)(r + 8) * C_ + cc] = l1;
            }
        return;
    }

    if (mode == 2) {
        // kp/vp scatter: row = b*288 + l; col picks k-vs-v, head, dim
        #pragma unroll
        for (int mt = 0; mt < 2; mt++)
            #pragma unroll
            for (int nt = 0; nt < 8; nt++) {
                int gc = col0 + ncol + nt * 8;       // 0..767
                int t  = gc / C_;                    // 0 -> kp, 1 -> vp
                int cc = gc - t * C_;
                int hh = cc / HD, d = cc % HD;       // d is even
                #pragma unroll
                for (int half = 0; half < 2; half++) {
                    int r = mrow + mt * 16 + half * 8;
                    int b = r / LP, l = r % LP;
                    float a0 = acc[mt][nt][half * 2 + 0];
                    float a1 = acc[mt][nt][half * 2 + 1];
                    if (t == 0) {
                        uint32_t hi, lo;
                        split_pack(a0, a1, hi, lo);
                        size_t o = ((size_t)(b * NH + hh) * LP + l) * HD + d;
                        *(uint32_t*)&g_kphi[o] = hi;
                        *(uint32_t*)&g_kplo[o] = lo;
                    } else {
                        __nv_bfloat16 b0 = __float2bfloat16(a0);
                        __nv_bfloat16 b1 = __float2bfloat16(a1);
                        size_t o0 = ((size_t)(b * NH + hh) * HD + d)     * LP + l;
                        size_t o1 = ((size_t)(b * NH + hh) * HD + d + 1) * LP + l;
                        g_vpthi[o0] = b0;
                        g_vptlo[o0] = __float2bfloat16(a0 - __bfloat162float(b0));
                        g_vpthi[o1] = b1;
                        g_vptlo[o1] = __float2bfloat16(a1 - __bfloat162float(b1));
                    }
                }
            }
        return;
    }

    // mode 1: projection output + bias
    #pragma unroll
    for (int mt = 0; mt < 2; mt++)
        #pragma unroll
        for (int nt = 0; nt < 8; nt++) {
            int r  = mrow + mt * 16;
            int cc = col0 + ncol + nt * 8;
            float2 v0 = make_float2(acc[mt][nt][0] + bias[cc],
                                    acc[mt][nt][1] + bias[cc + 1]);
            float2 v1 = make_float2(acc[mt][nt][2] + bias[cc],
                                    acc[mt][nt][3] + bias[cc + 1]);
            *(float2*)&Cout[(size_t)r * C_ + cc]       = v0;
            *(float2*)&Cout[(size_t)(r + 8) * C_ + cc] = v1;
        }
}

// ---------------------------------------------------------------------------
// Tensor-core attention. One CTA = one (b,h) x 256 q rows; 8 warps x 32 rows.
// KP [l][d] and VPt [d][l] staged in SMEM as bf16 hi/lo; Q frags in registers.
// No-max softmax in log2 domain (scale*log2e pre-folded into q).
// ---------------------------------------------------------------------------
#define QSTRIDE 56          // 48 + 8 pad  (conflict-free ldmatrix)
#define VSTRIDE 296         // 288 + 8 pad

#define SQH 0
#define SQL (SQH + 256 * QSTRIDE * 2)
#define SKH (SQL + 256 * QSTRIDE * 2)
#define SKL (SKH + LP * QSTRIDE * 2)
#define SVH (SKL + LP * QSTRIDE * 2)
#define SVL (SVH + HD * VSTRIDE * 2)
#define ATTN_SMEM (SVL + HD * VSTRIDE * 2)    // 178688 B

__global__ void __launch_bounds__(256, 1) attn_mma_kernel()
{
    extern __shared__ char sm[];

    const int tid  = threadIdx.x;
    const int lane = tid & 31;
    const int wid  = tid >> 5;
    const int bh   = blockIdx.y;
    const int b    = bh >> 3, h = bh & 7;
    const int n0   = blockIdx.x * 256;

    // ---- prologue: stage Q, KP, VPt into SMEM via cp.async ----
    {
        const uint4* qh = (const uint4*)(g_qhi + (size_t)(b * NPIX + n0) * C_ + h * HD);
        const uint4* ql = (const uint4*)(g_qlo + (size_t)(b * NPIX + n0) * C_ + h * HD);
        const uint32_t sbase = smem_u32(sm);
        for (int i = tid; i < 256 * 6; i += 256) {
            int r = i / 6, u = i % 6;
            CP16(sbase + SQH + r * (QSTRIDE * 2) + u * 16, qh + r * 48 + u);
            CP16(sbase + SQL + r * (QSTRIDE * 2) + u * 16, ql + r * 48 + u);
        }
        const uint4* kh = (const uint4*)(g_kphi + (size_t)bh * LP * HD);
        const uint4* kl = (const uint4*)(g_kplo + (size_t)bh * LP * HD);
        for (int i = tid; i < LP * 6; i += 256) {
            int r = i / 6, u = i % 6;
            CP16(sbase + SKH + r * (QSTRIDE * 2) + u * 16, kh + i);
            CP16(sbase + SKL + r * (QSTRIDE * 2) + u * 16, kl + i);
        }
        const uint4* vh = (const uint4*)(g_vpthi + (size_t)bh * HD * LP);
        const uint4* vl = (const uint4*)(g_vptlo + (size_t)bh * HD * LP);
        for (int i = tid; i < HD * 36; i += 256) {
            int r = i / 36, u = i % 36;
            CP16(sbase + SVH + r * (VSTRIDE * 2) + u * 16, vh + i);
            CP16(sbase + SVL + r * (VSTRIDE * 2) + u * 16, vl + i);
        }
        CP_COMMIT();
        CP_WAIT0();
    }
    __syncthreads();

    const int aRow = (lane & 15);
    const int aKof = (lane >> 4) * 8;
    const int bRow = (lane & 7) + ((lane >> 3) & 1) * 8;
    const int bKof = (lane >> 4) * 8;

    // ---- Q fragments (held in registers across the whole loop) ----
    uint32_t qh[3][2][4], ql[3][2][4];
    #pragma unroll
    for (int ks = 0; ks < 3; ks++)
        #pragma unroll
        for (int mt = 0; mt < 2; mt++) {
            int so = (wid * 32 + mt * 16 + aRow) * (QSTRIDE * 2) + (ks * 16 + aKof) * 2;
            ldm_x4(qh[ks][mt], smem_u32(sm + SQH + so));
            ldm_x4(ql[ks][mt], smem_u32(sm + SQL + so));
        }

    float o[2][6][4];
    #pragma unroll
    for (int mt = 0; mt < 2; mt++)
        #pragma unroll
        for (int nt = 0; nt < 6; nt++)
            #pragma unroll
            for (int e = 0; e < 4; e++) o[mt][nt][e] = 0.f;
    float rs[2][2] = {{0.f, 0.f}, {0.f, 0.f}};

    for (int chunk = 0; chunk < 9; chunk++) {
        // ---- S = Q * KP^T over 32 L-columns ----
        float s[2][4][4];
        #pragma unroll
        for (int mt = 0; mt < 2; mt++)
            #pragma unroll
            for (int nt = 0; nt < 4; nt++)
                #pragma unroll
                for (int e = 0; e < 4; e++) s[mt][nt][e] = 0.f;

        #pragma unroll
        for (int ks = 0; ks < 3; ks++) {
            uint32_t kbh[4][2], kbl[4][2];
            #pragma unroll
            for (int np = 0; np < 2; np++) {
                int so = (chunk * 32 + np * 16 + bRow) * (QSTRIDE * 2)
                       + (ks * 16 + bKof) * 2;
                uint32_t t[4];
                ldm_x4(t, smem_u32(sm + SKH + so));
                kbh[np * 2    ][0] = t[0]; kbh[np * 2    ][1] = t[2];
                kbh[np * 2 + 1][0] = t[1]; kbh[np * 2 + 1][1] = t[3];
                ldm_x4(t, smem_u32(sm + SKL + so));
                kbl[np * 2    ][0] = t[0]; kbl[np * 2    ][1] = t[2];
                kbl[np * 2 + 1][0] = t[1]; kbl[np * 2 + 1][1] = t[3];
            }
            #pragma unroll
            for (int mt = 0; mt < 2; mt++)
                #pragma unroll
                for (int nt = 0; nt < 4; nt++) {
                    mma_bf16(s[mt][nt], qh[ks][mt], kbh[nt]);
                    mma_bf16(s[mt][nt], qh[ks][mt], kbl[nt]);
                    mma_bf16(s[mt][nt], ql[ks][mt], kbh[nt]);
                }
        }

        // ---- softmax numerator: e = 2^s, masked past L_, row sums ----
        #pragma unroll
        for (int mt = 0; mt < 2; mt++)
            #pragma unroll
            for (int nt = 0; nt < 4; nt++)
                #pragma unroll
                for (int e = 0; e < 4; e++) {
                    float v = ex2f(s[mt][nt][e]);
                    if (chunk == 8) {
                        int col = 256 + nt * 8 + (lane & 3) * 2 + (e & 1);
                        if (col >= L_) v = 0.f;
                    }
                    s[mt][nt][e] = v;
                    rs[mt][e >> 1] += v;
                }

        // ---- O += P * VP  (P from S-fragments, register-level repack) ----
        #pragma unroll
        for (int ks2 = 0; ks2 < 2; ks2++) {
            uint32_t ph[2][4], pl[2][4];
            #pragma unroll
            for (int mt = 0; mt < 2; mt++) {
                split_pack(s[mt][2 * ks2][0],     s[mt][2 * ks2][1],     ph[mt][0], pl[mt][0]);
                split_pack(s[mt][2 * ks2][2],     s[mt][2 * ks2][3],     ph[mt][1], pl[mt][1]);
                split_pack(s[mt][2 * ks2 + 1][0], s[mt][2 * ks2 + 1][1], ph[mt][2], pl[mt][2]);
                split_pack(s[mt][2 * ks2 + 1][2], s[mt][2 * ks2 + 1][3], ph[mt][3], pl[mt][3]);
            }
            uint32_t vbh[6][2], vbl[6][2];
            #pragma unroll
            for (int np = 0; np < 3; np++) {
                int so = (np * 16 + bRow) * (VSTRIDE * 2)
                       + (chunk * 32 + ks2 * 16 + bKof) * 2;
                uint32_t t[4];
                ldm_x4(t, smem_u32(sm + SVH + so));
                vbh[np * 2    ][0] = t[0]; vbh[np * 2    ][1] = t[2];
                vbh[np * 2 + 1][0] = t[1]; vbh[np * 2 + 1][1] = t[3];
                ldm_x4(t, smem_u32(sm + SVL + so));
                vbl[np * 2    ][0] = t[0]; vbl[np * 2    ][1] = t[2];
                vbl[np * 2 + 1][0] = t[1]; vbl[np * 2 + 1][1] = t[3];
            }
            #pragma unroll
            for (int mt = 0; mt < 2; mt++)
                #pragma unroll
                for (int nt = 0; nt < 6; nt++) {
                    mma_bf16(o[mt][nt], ph[mt], vbh[nt]);
                    mma_bf16(o[mt][nt], ph[mt], vbl[nt]);
                    mma_bf16(o[mt][nt], pl[mt], vbh[nt]);
                }
        }
    }

    // ---- finalize: reduce row sums across the 4 lanes of each row ----
    #pragma unroll
    for (int mt = 0; mt < 2; mt++)
        #pragma unroll
        for (int rhalf = 0; rhalf < 2; rhalf++) {
            float v = rs[mt][rhalf];
            v += __shfl_xor_sync(0xFFFFFFFF, v, 1);
            v += __shfl_xor_sync(0xFFFFFFFF, v, 2);
            rs[mt][rhalf] = 1.f / v;
        }

    // ---- write attention output as bf16 hi/lo for the projection GEMM ----
    #pragma unroll
    for (int mt = 0; mt < 2; mt++) {
        int rbase = n0 + wid * 32 + mt * 16 + (lane >> 2);
        #pragma unroll
        for (int nt = 0; nt < 6; nt++) {
            int cc = h * HD + nt * 8 + (lane & 3) * 2;
            uint32_t h0, l0, h1, l1;
            split_pack(o[mt][nt][0] * rs[mt][0], o[mt][nt][1] * rs[mt][0], h0, l0);
            split_pack(o[mt][nt][2] * rs[mt][1], o[mt][nt][3] * rs[mt][1], h1, l1);
            size_t r0o = (size_t)(b * NPIX + rbase) * C_ + cc;
            size_t r1o = (size_t)(b * NPIX + rbase + 8) * C_ + cc;
            *(uint32_t*)&g_aohi[r0o] = h0;
            *(uint32_t*)&g_aolo[r0o] = l0;
            *(uint32_t*)&g_aohi[r1o] = h1;
            *(uint32_t*)&g_aolo[r1o] = l1;
        }
    }
}

// ---------------------------------------------------------------------------
// Entry point
// ---------------------------------------------------------------------------
extern "C" void kernel_launch(void* const* d_in, const int* in_sizes, int n_in,
                              void* d_out, int out_size)
{
    const float* x      = (const float*)d_in[0];
    const float* w_qkv  = (const float*)d_in[1];
    const float* w_proj = (const float*)d_in[2];
    const float* b_proj = (const float*)d_in[3];
    float* out = (float*)d_out;

    cudaFuncSetAttribute(attn_mma_kernel,
                         cudaFuncAttributeMaxDynamicSharedMemorySize,
                         ATTN_SMEM);
    cudaFuncSetAttribute(gemm_mma_kernel,
                         cudaFuncAttributeMaxDynamicSharedMemorySize,
                         GEMM_SMEM);

    // 0) fused conversion + pooling pipeline
    conv_w_kernel<<<(QKN * C_ + C_ * C_ + 255) / 256, 256>>>(w_qkv, w_proj);
    conv_pool16_kernel<<<dim3(256, B_), 192>>>(x);
    pool4_x_kernel<<<dim3(16, B_), C_>>>();
    pool21_x_kernel<<<B_, C_>>>();
    conv_xp_kernel<<<(MP_ * C_ / 4) / 256, 256>>>();

    // 1) Q GEMM (32768 x 384 x 384) -> q bf16 split, scaled
    gemm_mma_kernel<<<dim3(3, M_ / 128), 256, GEMM_SMEM>>>(nullptr, nullptr, 0);

    // 2) K/V GEMM on pooled rows (2304 x 768 x 384) -> kp / vp (transposed)
    gemm_mma_kernel<<<dim3(6, MP_ / 128), 256, GEMM_SMEM>>>(nullptr, nullptr, 2);

    // 3) tensor-core attention (writes ao hi/lo bf16)
    attn_mma_kernel<<<dim3(NPIX / 256, B_ * NH), 256, ATTN_SMEM>>>();

    // 4) projection + bias -> d_out
    gemm_mma_kernel<<<dim3(3, M_ / 128), 256, GEMM_SMEM>>>(out, b_proj, 1);
}

// round 8
// speedup vs baseline: 3.5242x; 1.0127x over previous
#include <cuda_runtime.h>
#include <cuda_bf16.h>
#include <cstdint>

// ---------------------------------------------------------------------------
// Problem constants
// ---------------------------------------------------------------------------
#define B_    8
#define NH    8
#define HD    48
#define HW    64
#define NPIX  4096            // 64*64
#define C_    384
#define M_    32768           // B_*NPIX
#define L_    277             // 1 + 4 + 16 + 256
#define LP    288             // padded L (9 chunks of 32)
#define QKN   1152            // 3*C_
#define MP_   (B_ * LP)       // 2304 pooled rows (padded)

// scale * log2(e), folded into the q-columns of w_qkv at conversion time
#define QSC   0.2082351519f

// ---------------------------------------------------------------------------
// Scratch (allocation-free rule: __device__ globals; zero-initialized)
// ---------------------------------------------------------------------------
__device__ float g_xp[MP_ * C_];               // pooled x: only s16 rows (21..276) written

__device__ __nv_bfloat16 g_qhi[M_ * C_];       // q (pre-scaled), split
__device__ __nv_bfloat16 g_qlo[M_ * C_];
__device__ __nv_bfloat16 g_xhi[M_ * C_];
__device__ __nv_bfloat16 g_xlo[M_ * C_];
__device__ __nv_bfloat16 g_xphi[MP_ * C_];     // pooled x, split (pad rows = 0)
__device__ __nv_bfloat16 g_xplo[MP_ * C_];
__device__ __nv_bfloat16 g_wqT_hi[QKN * C_];   // w_qkv transposed: [1152, 384]
__device__ __nv_bfloat16 g_wqT_lo[QKN * C_];
__device__ __nv_bfloat16 g_wpT_hi[C_ * C_];    // w_proj transposed: [384, 384]
__device__ __nv_bfloat16 g_wpT_lo[C_ * C_];
__device__ __nv_bfloat16 g_aohi[M_ * C_];      // attention output, split
__device__ __nv_bfloat16 g_aolo[M_ * C_];

__device__ __nv_bfloat16 g_kphi[B_ * NH * LP * HD];   // [bh][l(288)][d]
__device__ __nv_bfloat16 g_kplo[B_ * NH * LP * HD];
__device__ __nv_bfloat16 g_vpthi[B_ * NH * HD * LP];  // [bh][d][l(288)]
__device__ __nv_bfloat16 g_vptlo[B_ * NH * HD * LP];

// ---------------------------------------------------------------------------
// PTX helpers (sm_80+ only; no 'a'-suffix features)
// ---------------------------------------------------------------------------
__device__ __forceinline__ uint32_t smem_u32(const void* p) {
    uint32_t a;
    asm("{ .reg .u64 t; cvta.to.shared.u64 t, %1; cvt.u32.u64 %0, t; }"
        : "=r"(a) : "l"(p));
    return a;
}
__device__ __forceinline__ void ldm_x4(uint32_t* r, uint32_t addr) {
    asm volatile("ldmatrix.sync.aligned.m8n8.x4.shared.b16 {%0,%1,%2,%3}, [%4];"
        : "=r"(r[0]), "=r"(r[1]), "=r"(r[2]), "=r"(r[3]) : "r"(addr));
}
__device__ __forceinline__ void mma_bf16(float* c, const uint32_t* a,
                                         const uint32_t* b) {
    asm volatile(
        "mma.sync.aligned.m16n8k16.row.col.f32.bf16.bf16.f32 "
        "{%0,%1,%2,%3}, {%4,%5,%6,%7}, {%8,%9}, {%0,%1,%2,%3};"
        : "+f"(c[0]), "+f"(c[1]), "+f"(c[2]), "+f"(c[3])
        : "r"(a[0]), "r"(a[1]), "r"(a[2]), "r"(a[3]), "r"(b[0]), "r"(b[1]));
}
__device__ __forceinline__ float ex2f(float x) {
    float r;
    asm("ex2.approx.f32 %0, %1;" : "=f"(r) : "f"(x));
    return r;
}
__device__ __forceinline__ void split_pack(float a, float b,
                                           uint32_t& hi, uint32_t& lo) {
    __nv_bfloat162 h = __floats2bfloat162_rn(a, b);
    __nv_bfloat162 l = __floats2bfloat162_rn(a - __low2float(h),
                                             b - __high2float(h));
    hi = *(uint32_t*)&h;
    lo = *(uint32_t*)&l;
}
#define CP16(dst, src) \
    asm volatile("cp.async.cg.shared.global [%0], [%1], 16;" \
                 :: "r"(dst), "l"(src))
#define CP_COMMIT()  asm volatile("cp.async.commit_group;" ::: "memory")
#define CP_WAIT0()   asm volatile("cp.async.wait_group 0;" ::: "memory")

// ---------------------------------------------------------------------------
// Fused: x -> bf16 hi/lo conversion  +  s=16 pooling (cells partition pixels).
// grid (256 cells, 8 b), block 192: thread = channel pair (2c, 2c+1).
// ---------------------------------------------------------------------------
__global__ void conv_pool16_kernel(const float* __restrict__ x)
{
    const int c    = threadIdx.x * 2;
    const int cell = blockIdx.x;
    const int b    = blockIdx.y;
    const int ci = cell >> 4, cj = cell & 15;

    float s0 = 0.f, s1 = 0.f;
    #pragma unroll
    for (int dy = 0; dy < 4; dy++)
        #pragma unroll
        for (int dx = 0; dx < 4; dx++) {
            int n = (ci * 4 + dy) * HW + (cj * 4 + dx);
            size_t e = (size_t)(b * NPIX + n) * C_ + c;
            float2 v = *(const float2*)&x[e];
            uint32_t hi, lo;
            split_pack(v.x, v.y, hi, lo);
            ((uint32_t*)g_xhi)[e >> 1] = hi;
            ((uint32_t*)g_xlo)[e >> 1] = lo;
            s0 += v.x; s1 += v.y;
        }
    float2 o = make_float2(s0 * (1.f / 16.f), s1 * (1.f / 16.f));
    *(float2*)&g_xp[(size_t)(b * LP + 21 + cell) * C_ + c] = o;
}

// ---------------------------------------------------------------------------
// Fused pooled-x finisher: rows 0..20 (s1/s2/s4) computed on the fly from the
// s16 cells (exact: equal-size means of means); all 288 rows converted to
// bf16 hi/lo. One float4 per thread. Pad rows (>=277) read zero-init g_xp.
// ---------------------------------------------------------------------------
__global__ void conv_xp_kernel()
{
    const int i   = blockIdx.x * blockDim.x + threadIdx.x;  // float4 index
    const int row = i / 96;                                  // 96 float4 per row
    const int u   = i % 96;
    const int b   = row / LP, l = row % LP;

    float4 v;
    if (l >= 21) {
        v = ((const float4*)g_xp)[i];
    } else {
        const float4* base = (const float4*)(g_xp + (size_t)b * LP * C_);
        int ci0, ce, cj0;
        float inv;
        if (l == 0)      { ci0 = 0;                 cj0 = 0;                 ce = 16; inv = 1.f / 256.f; }
        else if (l < 5)  { int s = l - 1; ci0 = (s >> 1) * 8; cj0 = (s & 1) * 8; ce = 8; inv = 1.f / 64.f; }
        else             { int s = l - 5; ci0 = (s >> 2) * 4; cj0 = (s & 3) * 4; ce = 4; inv = 1.f / 16.f; }
        float4 s = make_float4(0.f, 0.f, 0.f, 0.f);
        for (int ci = ci0; ci < ci0 + ce; ci++)
            for (int cj = cj0; cj < cj0 + ce; cj++) {
                float4 t = base[(21 + ci * 16 + cj) * 96 + u];
                s.x += t.x; s.y += t.y; s.z += t.z; s.w += t.w;
            }
        v = make_float4(s.x * inv, s.y * inv, s.z * inv, s.w * inv);
    }

    uint32_t h0, l0, h1, l1;
    split_pack(v.x, v.y, h0, l0);
    split_pack(v.z, v.w, h1, l1);
    ((uint32_t*)g_xphi)[i * 2    ] = h0;
    ((uint32_t*)g_xphi)[i * 2 + 1] = h1;
    ((uint32_t*)g_xplo)[i * 2    ] = l0;
    ((uint32_t*)g_xplo)[i * 2 + 1] = l1;
}

// ---------------------------------------------------------------------------
// Tiled-transpose weight conversion: w[K,N] -> wT[N,K] bf16 hi/lo, coalesced
// both ways. QSC folded into the q-columns (n < 384) of w_qkv.
// grid 576 (432 wqkv tiles + 144 wp tiles), block (32, 8).
// ---------------------------------------------------------------------------
__global__ void conv_wT_kernel(const float* __restrict__ wqkv,
                               const float* __restrict__ wp)
{
    __shared__ float ts[32][33];
    int t = blockIdx.x;
    const float* src;
    __nv_bfloat16 *dh, *dl;
    int N;
    bool isq;
    if (t < 432) { src = wqkv; N = QKN; dh = g_wqT_hi; dl = g_wqT_lo; isq = true; }
    else         { t -= 432; src = wp; N = C_; dh = g_wpT_hi; dl = g_wpT_lo; isq = false; }

    const int tn = t % (N / 32), tk = t / (N / 32);
    const int tx = threadIdx.x, ty = threadIdx.y;

    #pragma unroll
    for (int it = 0; it < 4; it++) {
        int k = tk * 32 + ty + it * 8;
        ts[ty + it * 8][tx] = src[(size_t)k * N + tn * 32 + tx];
    }
    __syncthreads();

    #pragma unroll
    for (int it = 0; it < 4; it++) {
        int n = tn * 32 + ty + it * 8;
        int k = tk * 32 + tx;
        float v = ts[tx][ty + it * 8];
        if (isq && n < C_) v *= QSC;          // fold softmax scale into Wq
        __nv_bfloat16 h = __float2bfloat16(v);
        dh[(size_t)n * C_ + k] = h;
        dl[(size_t)n * C_ + k] = __float2bfloat16(v - __bfloat162float(h));
    }
}

// ---------------------------------------------------------------------------
// Tensor-core GEMM, cp.async 2-stage double-buffered.
//   C = A[*,384] * B^T, B stored [N,384]
// Block 128x128, 8 warps (4x2), warp tile 32x64, BK = 32, 12 K-chunks.
// mode 0: A = g_x (32768 rows), B = wqT cols 0..383     -> q bf16 split
// mode 2: A = g_xp (2304 rows), B = wqT cols 384..1151  -> kp/vp scatter
// mode 1: A = g_ao (32768 rows), B = wpT                -> Cout + bias
// ---------------------------------------------------------------------------
#define TILE_B  10240      // one 128-row tile, bytes
#define GSTG    (4 * TILE_B)
#define GEMM_SMEM (2 * GSTG)      // 81920 B

__global__ void __launch_bounds__(256) gemm_mma_kernel(
    float* __restrict__ Cout, const float* __restrict__ bias, int mode)
{
    extern __shared__ char gsm[];

    const int tid  = threadIdx.x;
    const int lane = tid & 31;
    const int wid  = tid >> 5;
    const int wm   = wid & 3;
    const int wn   = wid >> 2;

    const __nv_bfloat16* Ahi = (mode == 0) ? g_xhi : (mode == 2) ? g_xphi : g_aohi;
    const __nv_bfloat16* Alo = (mode == 0) ? g_xlo : (mode == 2) ? g_xplo : g_aolo;
    const __nv_bfloat16* Bhi = (mode == 1) ? g_wpT_hi : g_wqT_hi;
    const __nv_bfloat16* Blo = (mode == 1) ? g_wpT_lo : g_wqT_lo;
    const int bcol0 = (mode == 2) ? C_ : 0;

    const int row0 = blockIdx.y * 128;
    const int col0 = blockIdx.x * 128;

    const int r0 = (tid * 2)     >> 2, q0 = (tid * 2)     & 3;
    const int r1 = (tid * 2 + 1) >> 2, q1 = (tid * 2 + 1) & 3;

    auto issue_chunk = [&](int c, int stg) {
        const int koff = c * 32;
        char* sb = gsm + stg * GSTG;
        {
            size_t gA = (size_t)(row0 + r0) * C_ + koff + q0 * 8;
            size_t gB = (size_t)(bcol0 + col0 + r0) * C_ + koff + q0 * 8;
            uint32_t so = smem_u32(sb) + r0 * 80 + q0 * 16;
            CP16(so,              Ahi + gA);
            CP16(so + TILE_B,     Alo + gA);
            CP16(so + 2 * TILE_B, Bhi + gB);
            CP16(so + 3 * TILE_B, Blo + gB);
        }
        {
            size_t gA = (size_t)(row0 + r1) * C_ + koff + q1 * 8;
            size_t gB = (size_t)(bcol0 + col0 + r1) * C_ + koff + q1 * 8;
            uint32_t so = smem_u32(sb) + r1 * 80 + q1 * 16;
            CP16(so,              Ahi + gA);
            CP16(so + TILE_B,     Alo + gA);
            CP16(so + 2 * TILE_B, Bhi + gB);
            CP16(so + 3 * TILE_B, Blo + gB);
        }
        CP_COMMIT();
    };

    float acc[2][8][4];
    #pragma unroll
    for (int mt = 0; mt < 2; mt++)
        #pragma unroll
        for (int nt = 0; nt < 8; nt++)
            #pragma unroll
            for (int e = 0; e < 4; e++) acc[mt][nt][e] = 0.f;

    const int aRow = (lane & 15);
    const int aKof = (lane >> 4) * 8;
    const int bRow = (lane & 7) + ((lane >> 3) & 1) * 8;
    const int bKof = (lane >> 4) * 8;

    issue_chunk(0, 0);

    for (int c = 0; c < 12; c++) {
        CP_WAIT0();
        __syncthreads();
        if (c + 1 < 12) issue_chunk(c + 1, (c + 1) & 1);

        char* sb = gsm + (c & 1) * GSTG;
        const uint32_t sA  = smem_u32(sb);
        const uint32_t sB  = sA + 2 * TILE_B;

        #pragma unroll
        for (int ks = 0; ks < 2; ks++) {
            const int kk = ks * 16;
            uint32_t ah[2][4], al[2][4];
            #pragma unroll
            for (int mt = 0; mt < 2; mt++) {
                uint32_t so = (wm * 32 + mt * 16 + aRow) * 80 + (kk + aKof) * 2;
                ldm_x4(ah[mt], sA + so);
                ldm_x4(al[mt], sA + TILE_B + so);
            }
            uint32_t bh[8][2], bl[8][2];
            #pragma unroll
            for (int np = 0; np < 4; np++) {
                uint32_t so = (wn * 64 + np * 16 + bRow) * 80 + (kk + bKof) * 2;
                uint32_t t[4];
                ldm_x4(t, sB + so);
                bh[np * 2    ][0] = t[0]; bh[np * 2    ][1] = t[2];
                bh[np * 2 + 1][0] = t[1]; bh[np * 2 + 1][1] = t[3];
                ldm_x4(t, sB + TILE_B + so);
                bl[np * 2    ][0] = t[0]; bl[np * 2    ][1] = t[2];
                bl[np * 2 + 1][0] = t[1]; bl[np * 2 + 1][1] = t[3];
            }
            #pragma unroll
            for (int mt = 0; mt < 2; mt++)
                #pragma unroll
                for (int nt = 0; nt < 8; nt++) {
                    mma_bf16(acc[mt][nt], ah[mt], bh[nt]);
                    mma_bf16(acc[mt][nt], ah[mt], bl[nt]);
                    mma_bf16(acc[mt][nt], al[mt], bh[nt]);
                }
        }
    }

    // ---- epilogue ----
    const int mrow = row0 + wm * 32 + (lane >> 2);
    const int ncol = wn * 64 + (lane & 3) * 2;

    if (mode == 0) {
        // q (already scaled via weights): split to bf16 hi/lo
        #pragma unroll
        for (int mt = 0; mt < 2; mt++)
            #pragma unroll
            for (int nt = 0; nt < 8; nt++) {
                int r  = mrow + mt * 16;
                int cc = col0 + ncol + nt * 8;
                uint32_t h0, l0, h1, l1;
                split_pack(acc[mt][nt][0], acc[mt][nt][1], h0, l0);
                split_pack(acc[mt][nt][2], acc[mt][nt][3], h1, l1);
                *(uint32_t*)&g_qhi[(size_t)r * C_ + cc]       = h0;
                *(uint32_t*)&g_qlo[(size_t)r * C_ + cc]       = l0;
                *(uint32_t*)&g_qhi[(size_t)(r + 8) * C_ + cc] = h1;
                *(uint32_t*)&g_qlo[(size_t)(r + 8) * C_ + cc] = l1;
            }
        return;
    }

    if (mode == 2) {
        #pragma unroll
        for (int mt = 0; mt < 2; mt++)
            #pragma unroll
            for (int nt = 0; nt < 8; nt++) {
                int gc = col0 + ncol + nt * 8;       // 0..767
                int t  = gc / C_;                    // 0 -> kp, 1 -> vp
                int cc = gc - t * C_;
                int hh = cc / HD, d = cc % HD;       // d is even
                #pragma unroll
                for (int half = 0; half < 2; half++) {
                    int r = mrow + mt * 16 + half * 8;
                    int b = r / LP, l = r % LP;
                    float a0 = acc[mt][nt][half * 2 + 0];
                    float a1 = acc[mt][nt][half * 2 + 1];
                    if (t == 0) {
                        uint32_t hi, lo;
                        split_pack(a0, a1, hi, lo);
                        size_t o = ((size_t)(b * NH + hh) * LP + l) * HD + d;
                        *(uint32_t*)&g_kphi[o] = hi;
                        *(uint32_t*)&g_kplo[o] = lo;
                    } else {
                        __nv_bfloat16 b0 = __float2bfloat16(a0);
                        __nv_bfloat16 b1 = __float2bfloat16(a1);
                        size_t o0 = ((size_t)(b * NH + hh) * HD + d)     * LP + l;
                        size_t o1 = ((size_t)(b * NH + hh) * HD + d + 1) * LP + l;
                        g_vpthi[o0] = b0;
                        g_vptlo[o0] = __float2bfloat16(a0 - __bfloat162float(b0));
                        g_vpthi[o1] = b1;
                        g_vptlo[o1] = __float2bfloat16(a1 - __bfloat162float(b1));
                    }
                }
            }
        return;
    }

    // mode 1: projection output + bias
    #pragma unroll
    for (int mt = 0; mt < 2; mt++)
        #pragma unroll
        for (int nt = 0; nt < 8; nt++) {
            int r  = mrow + mt * 16;
            int cc = col0 + ncol + nt * 8;
            float2 v0 = make_float2(acc[mt][nt][0] + bias[cc],
                                    acc[mt][nt][1] + bias[cc + 1]);
            float2 v1 = make_float2(acc[mt][nt][2] + bias[cc],
                                    acc[mt][nt][3] + bias[cc + 1]);
            *(float2*)&Cout[(size_t)r * C_ + cc]       = v0;
            *(float2*)&Cout[(size_t)(r + 8) * C_ + cc] = v1;
        }
}

// ---------------------------------------------------------------------------
// Tensor-core attention, 16 warps (512 threads): one CTA = one (b,h) x 256
// q rows; each warp owns 16 rows -> 4 warps/SMSP for latency hiding.
// KP [l][d] and VPt [d][l] staged in SMEM as bf16 hi/lo; Q frags in registers.
// No-max softmax in log2 domain (scale*log2e pre-folded into Wq).
// ---------------------------------------------------------------------------
#define QSTRIDE 56          // 48 + 8 pad  (conflict-free ldmatrix)
#define VSTRIDE 296         // 288 + 8 pad

#define SQH 0
#define SQL (SQH + 256 * QSTRIDE * 2)
#define SKH (SQL + 256 * QSTRIDE * 2)
#define SKL (SKH + LP * QSTRIDE * 2)
#define SVH (SKL + LP * QSTRIDE * 2)
#define SVL (SVH + HD * VSTRIDE * 2)
#define ATTN_SMEM (SVL + HD * VSTRIDE * 2)    // 178688 B

__global__ void __launch_bounds__(512, 1) attn_mma_kernel()
{
    extern __shared__ char sm[];

    const int tid  = threadIdx.x;
    const int lane = tid & 31;
    const int wid  = tid >> 5;          // 0..15, each warp = 16 q rows
    const int bh   = blockIdx.y;
    const int b    = bh >> 3, h = bh & 7;
    const int n0   = blockIdx.x * 256;

    // ---- prologue: stage Q, KP, VPt into SMEM via cp.async ----
    {
        const uint4* qh = (const uint4*)(g_qhi + (size_t)(b * NPIX + n0) * C_ + h * HD);
        const uint4* ql = (const uint4*)(g_qlo + (size_t)(b * NPIX + n0) * C_ + h * HD);
        const uint32_t sbase = smem_u32(sm);
        for (int i = tid; i < 256 * 6; i += 512) {
            int r = i / 6, u = i % 6;
            CP16(sbase + SQH + r * (QSTRIDE * 2) + u * 16, qh + r * 48 + u);
            CP16(sbase + SQL + r * (QSTRIDE * 2) + u * 16, ql + r * 48 + u);
        }
        const uint4* kh = (const uint4*)(g_kphi + (size_t)bh * LP * HD);
        const uint4* kl = (const uint4*)(g_kplo + (size_t)bh * LP * HD);
        for (int i = tid; i < LP * 6; i += 512) {
            int r = i / 6, u = i % 6;
            CP16(sbase + SKH + r * (QSTRIDE * 2) + u * 16, kh + i);
            CP16(sbase + SKL + r * (QSTRIDE * 2) + u * 16, kl + i);
        }
        const uint4* vh = (const uint4*)(g_vpthi + (size_t)bh * HD * LP);
        const uint4* vl = (const uint4*)(g_vptlo + (size_t)bh * HD * LP);
        for (int i = tid; i < HD * 36; i += 512) {
            int r = i / 36, u = i % 36;
            CP16(sbase + SVH + r * (VSTRIDE * 2) + u * 16, vh + i);
            CP16(sbase + SVL + r * (VSTRIDE * 2) + u * 16, vl + i);
        }
        CP_COMMIT();
        CP_WAIT0();
    }
    __syncthreads();

    const int aRow = (lane & 15);
    const int aKof = (lane >> 4) * 8;
    const int bRow = (lane & 7) + ((lane >> 3) & 1) * 8;
    const int bKof = (lane >> 4) * 8;

    // ---- Q fragments: this warp's 16 rows, all 48 dims ----
    uint32_t qh[3][4], ql[3][4];
    #pragma unroll
    for (int ks = 0; ks < 3; ks++) {
        int so = (wid * 16 + aRow) * (QSTRIDE * 2) + (ks * 16 + aKof) * 2;
        ldm_x4(qh[ks], smem_u32(sm + SQH + so));
        ldm_x4(ql[ks], smem_u32(sm + SQL + so));
    }

    float o[6][4];
    #pragma unroll
    for (int nt = 0; nt < 6; nt++)
        #pragma unroll
        for (int e = 0; e < 4; e++) o[nt][e] = 0.f;
    float rs[2] = {0.f, 0.f};

    for (int chunk = 0; chunk < 9; chunk++) {
        // ---- S = Q * KP^T over 32 L-columns ----
        float s[4][4];
        #pragma unroll
        for (int nt = 0; nt < 4; nt++)
            #pragma unroll
            for (int e = 0; e < 4; e++) s[nt][e] = 0.f;

        #pragma unroll
        for (int ks = 0; ks < 3; ks++) {
            uint32_t kbh[4][2], kbl[4][2];
            #pragma unroll
            for (int np = 0; np < 2; np++) {
                int so = (chunk * 32 + np * 16 + bRow) * (QSTRIDE * 2)
                       + (ks * 16 + bKof) * 2;
                uint32_t t[4];
                ldm_x4(t, smem_u32(sm + SKH + so));
                kbh[np * 2    ][0] = t[0]; kbh[np * 2    ][1] = t[2];
                kbh[np * 2 + 1][0] = t[1]; kbh[np * 2 + 1][1] = t[3];
                ldm_x4(t, smem_u32(sm + SKL + so));
                kbl[np * 2    ][0] = t[0]; kbl[np * 2    ][1] = t[2];
                kbl[np * 2 + 1][0] = t[1]; kbl[np * 2 + 1][1] = t[3];
            }
            #pragma unroll
            for (int nt = 0; nt < 4; nt++) {
                mma_bf16(s[nt], qh[ks], kbh[nt]);
                mma_bf16(s[nt], qh[ks], kbl[nt]);
                mma_bf16(s[nt], ql[ks], kbh[nt]);
            }
        }

        // ---- softmax numerator: e = 2^s, masked past L_, row sums ----
        #pragma unroll
        for (int nt = 0; nt < 4; nt++)
            #pragma unroll
            for (int e = 0; e < 4; e++) {
                float v = ex2f(s[nt][e]);
                if (chunk == 8) {
                    int col = 256 + nt * 8 + (lane & 3) * 2 + (e & 1);
                    if (col >= L_) v = 0.f;
                }
                s[nt][e] = v;
                rs[e >> 1] += v;
            }

        // ---- O += P * VP  (P from S-fragments, register-level repack) ----
        #pragma unroll
        for (int ks2 = 0; ks2 < 2; ks2++) {
            uint32_t ph[4], pl[4];
            split_pack(s[2 * ks2][0],     s[2 * ks2][1],     ph[0], pl[0]);
            split_pack(s[2 * ks2][2],     s[2 * ks2][3],     ph[1], pl[1]);
            split_pack(s[2 * ks2 + 1][0], s[2 * ks2 + 1][1], ph[2], pl[2]);
            split_pack(s[2 * ks2 + 1][2], s[2 * ks2 + 1][3], ph[3], pl[3]);

            uint32_t vbh[6][2], vbl[6][2];
            #pragma unroll
            for (int np = 0; np < 3; np++) {
                int so = (np * 16 + bRow) * (VSTRIDE * 2)
                       + (chunk * 32 + ks2 * 16 + bKof) * 2;
                uint32_t t[4];
                ldm_x4(t, smem_u32(sm + SVH + so));
                vbh[np * 2    ][0] = t[0]; vbh[np * 2    ][1] = t[2];
                vbh[np * 2 + 1][0] = t[1]; vbh[np * 2 + 1][1] = t[3];
                ldm_x4(t, smem_u32(sm + SVL + so));
                vbl[np * 2    ][0] = t[0]; vbl[np * 2    ][1] = t[2];
                vbl[np * 2 + 1][0] = t[1]; vbl[np * 2 + 1][1] = t[3];
            }
            #pragma unroll
            for (int nt = 0; nt < 6; nt++) {
                mma_bf16(o[nt], ph, vbh[nt]);
                mma_bf16(o[nt], ph, vbl[nt]);
                mma_bf16(o[nt], pl, vbh[nt]);
            }
        }
    }

    // ---- finalize: reduce row sums across the 4 lanes of each row ----
    #pragma unroll
    for (int rhalf = 0; rhalf < 2; rhalf++) {
        float v = rs[rhalf];
        v += __shfl_xor_sync(0xFFFFFFFF, v, 1);
        v += __shfl_xor_sync(0xFFFFFFFF, v, 2);
        rs[rhalf] = 1.f / v;
    }

    // ---- write attention output as bf16 hi/lo for the projection GEMM ----
    const int rbase = n0 + wid * 16 + (lane >> 2);
    #pragma unroll
    for (int nt = 0; nt < 6; nt++) {
        int cc = h * HD + nt * 8 + (lane & 3) * 2;
        uint32_t h0, l0, h1, l1;
        split_pack(o[nt][0] * rs[0], o[nt][1] * rs[0], h0, l0);
        split_pack(o[nt][2] * rs[1], o[nt][3] * rs[1], h1, l1);
        size_t r0o = (size_t)(b * NPIX + rbase) * C_ + cc;
        size_t r1o = (size_t)(b * NPIX + rbase + 8) * C_ + cc;
        *(uint32_t*)&g_aohi[r0o] = h0;
        *(uint32_t*)&g_aolo[r0o] = l0;
        *(uint32_t*)&g_aohi[r1o] = h1;
        *(uint32_t*)&g_aolo[r1o] = l1;
    }
}

// ---------------------------------------------------------------------------
// Entry point
// ---------------------------------------------------------------------------
extern "C" void kernel_launch(void* const* d_in, const int* in_sizes, int n_in,
                              void* d_out, int out_size)
{
    const float* x      = (const float*)d_in[0];
    const float* w_qkv  = (const float*)d_in[1];
    const float* w_proj = (const float*)d_in[2];
    const float* b_proj = (const float*)d_in[3];
    float* out = (float*)d_out;

    cudaFuncSetAttribute(attn_mma_kernel,
                         cudaFuncAttributeMaxDynamicSharedMemorySize,
                         ATTN_SMEM);
    cudaFuncSetAttribute(gemm_mma_kernel,
                         cudaFuncAttributeMaxDynamicSharedMemorySize,
                         GEMM_SMEM);

    // 0) conversions + pooling (pooling commutes with K/V projection)
    conv_wT_kernel<<<576, dim3(32, 8)>>>(w_qkv, w_proj);
    conv_pool16_kernel<<<dim3(256, B_), 192>>>(x);
    conv_xp_kernel<<<(MP_ * C_ / 4) / 256, 256>>>();

    // 1) Q GEMM (32768 x 384 x 384) -> q bf16 split (scale folded in weights)
    gemm_mma_kernel<<<dim3(3, M_ / 128), 256, GEMM_SMEM>>>(nullptr, nullptr, 0);

    // 2) K/V GEMM on pooled rows (2304 x 768 x 384) -> kp / vp (transposed)
    gemm_mma_kernel<<<dim3(6, MP_ / 128), 256, GEMM_SMEM>>>(nullptr, nullptr, 2);

    // 3) tensor-core attention, 16 warps (writes ao hi/lo bf16)
    attn_mma_kernel<<<dim3(NPIX / 256, B_ * NH), 512, ATTN_SMEM>>>();

    // 4) projection + bias -> d_out
    gemm_mma_kernel<<<dim3(3, M_ / 128), 256, GEMM_SMEM>>>(out, b_proj, 1);
}